// round 13
// baseline (speedup 1.0000x reference)
#include <cuda_runtime.h>
#include <cuda_bf16.h>
#include <cuda_fp16.h>
#include <math.h>
#include <float.h>
#include <stdint.h>

// ---------------- problem constants ----------------
#define SEQ   2048
#define DIM   1024
#define DEPTH 4
#define HEADS 16
#define DH    64
#define FFD   4096
#define VOCAB 32000

// ---------------- scratch (static device globals) ----------------
__device__ float g_x   [SEQ * DIM];
__device__ float g_qkv [SEQ * 3 * DIM];
__device__ __nv_bfloat16 g_ab [SEQ * 3 * DIM];
__device__ __nv_bfloat16 g_ab2[SEQ * 3 * FFD];
__device__ __nv_bfloat16 g_wb [133431296ull];
__device__ __align__(16) __nv_bfloat16 g_qs[6291456ull];  // Q tiles [h][ib64][64][192]
__device__ __align__(16) __nv_bfloat16 g_ks[6291456ull];  // K tiles [h][jb][192][64]
__device__ __align__(16) __nv_bfloat16 g_vs[6291456ull];  // V tiles [h][jb][192][64]

// weight offsets in g_wb (2-byte elements)
#define WB_QKV(l)  ((size_t)(l) * 6291456ull)                 // fp16 hi only
#define WB_OUT(l)  (25165824ull + (size_t)(l) * 2097152ull)   // fp16 hi only
#define WB_FF1(l)  (33554432ull + (size_t)(l) * 8388608ull)   // fp16 hi only
#define WB_FF2(l)  (67108864ull + (size_t)(l) * 8388608ull)   // fp16 hi only
#define WB_LOGITS  100663296ull                               // fp16 hi only

// ---------------- helpers ----------------
__device__ __forceinline__ uint32_t smem_u32(const void* p) {
    return (uint32_t)__cvta_generic_to_shared(p);
}
__device__ __forceinline__ void cp16(uint32_t s, const void* g) {
    asm volatile("cp.async.cg.shared.global [%0], [%1], 16;" :: "r"(s), "l"(g));
}
__device__ __forceinline__ uint32_t pack_bf16(float a, float b) {
    __nv_bfloat162 t = __floats2bfloat162_rn(a, b);
    return *(uint32_t*)&t;
}

// ---------------- weight split bf16: fp32[K,N] -> [Bhi ; Blo] bf16[2K,N] ----
__global__ void __launch_bounds__(256) convw_kernel(const float4* __restrict__ w,
                                                    __nv_bfloat16* __restrict__ o,
                                                    long long KN4) {
    long long idx = (long long)blockIdx.x * 256 + threadIdx.x;
    if (idx >= KN4) return;
    float4 v = w[idx];
    union { unsigned short u[4]; uint2 p; } hi4, lo4;
    float vv[4] = {v.x, v.y, v.z, v.w};
    #pragma unroll
    for (int e = 0; e < 4; e++) {
        __nv_bfloat16 hi = __float2bfloat16_rn(vv[e]);
        __nv_bfloat16 lo = __float2bfloat16_rn(vv[e] - __bfloat162float(hi));
        hi4.u[e] = *(unsigned short*)&hi;
        lo4.u[e] = *(unsigned short*)&lo;
    }
    long long KN = KN4 * 4;
    *(uint2*)(o + 4 * idx)      = hi4.p;
    *(uint2*)(o + KN + 4 * idx) = lo4.p;
}

// ---------------- weight conv fp16 (hi only) ----------------
__global__ void __launch_bounds__(256) convw_f16_kernel(const float4* __restrict__ w,
                                                        __half* __restrict__ o,
                                                        long long KN4) {
    long long idx = (long long)blockIdx.x * 256 + threadIdx.x;
    if (idx >= KN4) return;
    float4 v = w[idx];
    union { __half u[4]; uint2 p; } h4;
    h4.u[0] = __float2half_rn(v.x); h4.u[1] = __float2half_rn(v.y);
    h4.u[2] = __float2half_rn(v.z); h4.u[3] = __float2half_rn(v.w);
    *(uint2*)(o + 4 * idx) = h4.p;
}

// ---------------- embed ----------------
__global__ void __launch_bounds__(256) embed_kernel(const int* __restrict__ tokens,
                                                    const float* __restrict__ emb,
                                                    float* __restrict__ x) {
    int idx = blockIdx.x * 256 + threadIdx.x;
    int row = idx >> 10;
    int d   = idx & 1023;
    x[idx] = emb[(size_t)tokens[row] * DIM + d];
}

// ---------------- rmsnorm + split fp16 2-term: A' = [hi | lo] ----
__global__ void __launch_bounds__(256) rmsnorm_split_f16_kernel(const float* __restrict__ x,
                                                                const float* __restrict__ gamma,
                                                                __half* __restrict__ ab) {
    int row = blockIdx.x;
    const float* xr = x + (size_t)row * DIM;
    float ss = 0.f;
    for (int i = threadIdx.x; i < DIM; i += 256) { float v = xr[i]; ss += v * v; }
    __shared__ float red[256];
    red[threadIdx.x] = ss;
    __syncthreads();
    for (int s = 128; s > 0; s >>= 1) {
        if (threadIdx.x < s) red[threadIdx.x] += red[threadIdx.x + s];
        __syncthreads();
    }
    float scale = 32.0f / fmaxf(sqrtf(red[0]), 1e-12f);
    __half* ar = ab + (size_t)row * (2 * DIM);
    for (int i = threadIdx.x; i < DIM; i += 256) {
        float v = xr[i] * scale * gamma[i];
        __half hi = __float2half_rn(v);
        __half lo = __float2half_rn(v - __half2float(hi));
        ar[i] = hi;
        ar[DIM + i] = lo;
    }
}

// ---------------- rmsnorm fp16 1-term (logits A) ----------------
__global__ void __launch_bounds__(256) rmsnorm_f16_kernel(const float* __restrict__ x,
                                                          const float* __restrict__ gamma,
                                                          __half* __restrict__ ab) {
    int row = blockIdx.x;
    const float* xr = x + (size_t)row * DIM;
    float ss = 0.f;
    for (int i = threadIdx.x; i < DIM; i += 256) { float v = xr[i]; ss += v * v; }
    __shared__ float red[256];
    red[threadIdx.x] = ss;
    __syncthreads();
    for (int s = 128; s > 0; s >>= 1) {
        if (threadIdx.x < s) red[threadIdx.x] += red[threadIdx.x + s];
        __syncthreads();
    }
    float scale = 32.0f / fmaxf(sqrtf(red[0]), 1e-12f);
    __half* ar = ab + (size_t)row * DIM;
    for (int i = threadIdx.x; i < DIM; i += 256)
        ar[i] = __float2half_rn(xr[i] * scale * gamma[i]);
}

// ---------------- Q split (rotary fused, scaled): -> [h][ib64][64][192] --------------
#define L2_10000 13.287712379549449f
__global__ void __launch_bounds__(256) qsplit_kernel(const float* __restrict__ qkv,
                                                     __nv_bfloat16* __restrict__ Qsp) {
    int ib = blockIdx.x, h = blockIdx.y;
    int tid = threadIdx.x;
    __nv_bfloat16* qt = Qsp + ((size_t)h * 32 + ib) * (64 * 192);
    #pragma unroll
    for (int l = 0; l < 16; l++) {
        int e = tid + l * 256;
        int i = e >> 6, d = e & 63;
        int pos = ib * 64 + i;
        const float* qrow = qkv + (size_t)pos * (3 * DIM) + h * DH;
        float x = qrow[d];
        float other = qrow[d ^ 32];
        int j = d & 31;
        float inv = exp2f((float)j * (-L2_10000 / 32.0f));
        float fr = (float)pos * inv;
        float c, s;
        sincosf(fr, &s, &c);
        float val = ((d < 32) ? (x * c - other * s) : (x * c + other * s)) * 0.125f;
        __nv_bfloat16 hi = __float2bfloat16_rn(val);
        __nv_bfloat16 lo = __float2bfloat16_rn(val - __bfloat162float(hi));
        qt[(size_t)i * 192 + d]       = hi;
        qt[(size_t)i * 192 + 64 + d]  = lo;
        qt[(size_t)i * 192 + 128 + d] = hi;
    }
}

// ---------------- K/V split (K rotary fused, K transposed): -> [h][jb][192][64] ------
__global__ void __launch_bounds__(256) kvsplit_kernel(const float* __restrict__ qkv,
                                                      __nv_bfloat16* __restrict__ Ksp,
                                                      __nv_bfloat16* __restrict__ Vsp) {
    __shared__ float kt_s[64][65];
    int jb = blockIdx.x, h = blockIdx.y;
    int tid = threadIdx.x;
    __nv_bfloat16* kt = Ksp + ((size_t)h * 32 + jb) * (192 * 64);
    __nv_bfloat16* vt = Vsp + ((size_t)h * 32 + jb) * (192 * 64);
    #pragma unroll
    for (int l = 0; l < 16; l++) {
        int e = tid + l * 256;
        int j = e >> 6, d = e & 63;
        int pos = jb * 64 + j;
        const float* krow = qkv + (size_t)pos * (3 * DIM) + (HEADS + h) * DH;
        float x = krow[d];
        float other = krow[d ^ 32];
        int jj = d & 31;
        float inv = exp2f((float)jj * (-L2_10000 / 32.0f));
        float fr = (float)pos * inv;
        float c, s;
        sincosf(fr, &s, &c);
        kt_s[d][j] = (d < 32) ? (x * c - other * s) : (x * c + other * s);
        const float* vrow = qkv + (size_t)pos * (3 * DIM) + (2 * HEADS + h) * DH;
        float v = vrow[d];
        __nv_bfloat16 vh = __float2bfloat16_rn(v);
        __nv_bfloat16 vl = __float2bfloat16_rn(v - __bfloat162float(vh));
        vt[(size_t)j * 64 + d]         = vh;
        vt[(size_t)(64 + j) * 64 + d]  = vh;
        vt[(size_t)(128 + j) * 64 + d] = vl;
    }
    __syncthreads();
    #pragma unroll
    for (int l = 0; l < 16; l++) {
        int e = tid + l * 256;
        int d = e >> 6, j = e & 63;
        float val = kt_s[d][j];
        __nv_bfloat16 hi = __float2bfloat16_rn(val);
        __nv_bfloat16 lo = __float2bfloat16_rn(val - __bfloat162float(hi));
        kt[(size_t)d * 64 + j]         = hi;
        kt[(size_t)(64 + d) * 64 + j]  = hi;
        kt[(size_t)(128 + d) * 64 + j] = lo;
    }
}

// ---------------- mma primitives ----------------
#define LDSM4(R0,R1,R2,R3,addr) \
    asm volatile("ldmatrix.sync.aligned.m8n8.x4.shared.b16 {%0,%1,%2,%3},[%4];" \
        : "=r"(R0),"=r"(R1),"=r"(R2),"=r"(R3) : "r"(addr))
#define LDSM4T(R0,R1,R2,R3,addr) \
    asm volatile("ldmatrix.sync.aligned.m8n8.x4.trans.shared.b16 {%0,%1,%2,%3},[%4];" \
        : "=r"(R0),"=r"(R1),"=r"(R2),"=r"(R3) : "r"(addr))

template<bool F16>
__device__ __forceinline__ void mma_op(float* d, const uint32_t* a, uint32_t b0, uint32_t b1) {
    if (F16)
        asm volatile("mma.sync.aligned.m16n8k16.row.col.f32.f16.f16.f32 "
            "{%0,%1,%2,%3},{%4,%5,%6,%7},{%8,%9},{%0,%1,%2,%3};"
            : "+f"(d[0]),"+f"(d[1]),"+f"(d[2]),"+f"(d[3])
            : "r"(a[0]),"r"(a[1]),"r"(a[2]),"r"(a[3]),"r"(b0),"r"(b1));
    else
        asm volatile("mma.sync.aligned.m16n8k16.row.col.f32.bf16.bf16.f32 "
            "{%0,%1,%2,%3},{%4,%5,%6,%7},{%8,%9},{%0,%1,%2,%3};"
            : "+f"(d[0]),"+f"(d[1]),"+f"(d[2]),"+f"(d[3])
            : "r"(a[0]),"r"(a[1]),"r"(a[2]),"r"(a[3]),"r"(b0),"r"(b1));
}

// ---------------- tensor-core GEMM (K-chunk 64, 3 stages, frag dbuf) ----
// SPLITM: 0 = fp32 C (optional RES), 2 = fp16 2-term A'-format
#define A_STG_B 18432
#define B_STG_B 17408
#define SSTG_B  (A_STG_B + B_STG_B)
#define GEMM_SMEM (3 * SSTG_B)

template<int TERMS, bool F16, bool BIAS, bool RES, bool GELU, int SPLITM>
__global__ void __launch_bounds__(256, 2)
bgemm_kernel(const __nv_bfloat16* __restrict__ A,
             const __nv_bfloat16* __restrict__ B,
             const float* __restrict__ bias,
             float* __restrict__ C,
             __nv_bfloat16* __restrict__ Cs,
             int N, int Ku64)
{
    extern __shared__ __align__(16) __nv_bfloat16 sm[];
    uint32_t sbase = smem_u32(sm);

    int tid  = threadIdx.x;
    int lane = tid & 31;
    int warp = tid >> 5;
    int wm = warp >> 2;
    int wn = warp & 3;
    int bm = blockIdx.x * 128;
    int bn = blockIdx.y * 128;
    int Astride = TERMS * Ku64 * 64;

    const char* gAbase = (const char*)(A + (size_t)bm * Astride);
    const char* gBbase = (const char*)(B + bn);

    uint32_t aFrag = (uint32_t)(((wm * 64 + (lane & 15)) * 72 + (lane >> 4) * 8) * 2);
    uint32_t bFrag = (uint32_t)(A_STG_B + ((lane & 15) * 136 + wn * 32 + (lane >> 4) * 8) * 2);

    float acc[4][4][4];
    #pragma unroll
    for (int i = 0; i < 4; i++)
        #pragma unroll
        for (int j = 0; j < 4; j++)
            #pragma unroll
            for (int k = 0; k < 4; k++) acc[i][j][k] = 0.f;

    int steps = TERMS * Ku64;

    auto load_stage = [&](int t) {
        uint32_t so = sbase + (uint32_t)(t % 3) * SSTG_B;
        int bs = (t < Ku64) ? t : t - Ku64;
        const char* aP = gAbase + (size_t)t * 128;
        const char* bP = gBbase + (size_t)bs * ((size_t)N * 128);
        #pragma unroll
        for (int j = 0; j < 4; j++) {
            int i = tid + j * 256;
            cp16(so + (uint32_t)(((i >> 3) * 72 + (i & 7) * 8) * 2),
                 aP + (size_t)(i >> 3) * Astride * 2 + (i & 7) * 16);
            cp16(so + (uint32_t)(A_STG_B + ((i >> 4) * 136 + (i & 15) * 8) * 2),
                 bP + (size_t)(i >> 4) * N * 2 + (i & 15) * 16);
        }
        asm volatile("cp.async.commit_group;" ::: "memory");
    };

    load_stage(0);
    load_stage(1);

    uint32_t af[2][16], bf[2][8];

    auto ldsA = [&](uint32_t* f, uint32_t stg, int kk) {
        #pragma unroll
        for (int mt = 0; mt < 4; mt++) {
            uint32_t addr = stg + aFrag + mt * (16 * 72 * 2) + kk * 32;
            LDSM4(f[mt * 4 + 0], f[mt * 4 + 1], f[mt * 4 + 2], f[mt * 4 + 3], addr);
        }
    };
    auto ldsB = [&](uint32_t* f, uint32_t stg, int kk) {
        #pragma unroll
        for (int p = 0; p < 2; p++) {
            uint32_t addr = stg + bFrag + p * 32 + kk * (16 * 136 * 2);
            LDSM4T(f[p * 4 + 0], f[p * 4 + 1], f[p * 4 + 2], f[p * 4 + 3], addr);
        }
    };

    for (int t = 0; t < steps; t++) {
        if (t + 1 < steps) asm volatile("cp.async.wait_group 1;" ::: "memory");
        else               asm volatile("cp.async.wait_group 0;" ::: "memory");
        __syncthreads();
        if (t + 2 < steps) load_stage(t + 2);

        uint32_t stg = sbase + (uint32_t)(t % 3) * SSTG_B;
        ldsA(af[0], stg, 0);
        ldsB(bf[0], stg, 0);
        #pragma unroll
        for (int kk = 0; kk < 4; kk++) {
            int cur = kk & 1, nxt = cur ^ 1;
            if (kk < 3) { ldsA(af[nxt], stg, kk + 1); ldsB(bf[nxt], stg, kk + 1); }
            #pragma unroll
            for (int mt = 0; mt < 4; mt++) {
                #pragma unroll
                for (int nt = 0; nt < 4; nt++) {
                    uint32_t b0 = bf[cur][(nt >> 1) * 4 + (nt & 1) * 2];
                    uint32_t b1 = bf[cur][(nt >> 1) * 4 + (nt & 1) * 2 + 1];
                    mma_op<F16>(acc[mt][nt], &af[cur][mt * 4], b0, b1);
                }
            }
        }
    }

    int row0 = bm + wm * 64;
    int col0 = bn + wn * 32;
    #pragma unroll
    for (int mt = 0; mt < 4; mt++) {
        #pragma unroll
        for (int nt = 0; nt < 4; nt++) {
            int r = row0 + mt * 16 + (lane >> 2);
            int c = col0 + nt * 8 + (lane & 3) * 2;
            #pragma unroll
            for (int half = 0; half < 2; half++) {
                int rr = r + half * 8;
                #pragma unroll
                for (int e = 0; e < 2; e++) {
                    float val = acc[mt][nt][half * 2 + e];
                    int cc = c + e;
                    if (BIAS) val += bias[cc];
                    if (GELU) val = 0.5f * val * (1.0f + erff(val * 0.70710678118654752f));
                    if (SPLITM == 2) {
                        __half* Ch = (__half*)Cs;
                        __half hi = __float2half_rn(val);
                        __half lo = __float2half_rn(val - __half2float(hi));
                        size_t base = (size_t)rr * (2 * (size_t)N);
                        Ch[base + cc] = hi;
                        Ch[base + N + cc] = lo;
                    } else {
                        size_t off = (size_t)rr * N + cc;
                        if (RES) val += C[off];
                        C[off] = val;
                    }
                }
            }
        }
    }
}

// ---------------- flash attention: Q=128 rows, 8 warps, double-buffered K/V ----------
// Qs [128][200] bf16 (51200 B); KV buf p: K [192][72] + V [192][72] (55296 B each)
#define FLQ_B  (128 * 200 * 2)
#define FLKV_B (192 * 72 * 2 * 2)
#define FL_SMEM (FLQ_B + 2 * FLKV_B)     // 161792 bytes

__global__ void __launch_bounds__(256) flash_kernel(const __nv_bfloat16* __restrict__ Qsp,
                                                    const __nv_bfloat16* __restrict__ Ksp,
                                                    const __nv_bfloat16* __restrict__ Vsp,
                                                    __half* __restrict__ ab) {
    extern __shared__ __align__(16) __nv_bfloat16 fsm[];
    uint32_t qsmem  = smem_u32(fsm);
    uint32_t kvbase = qsmem + FLQ_B;

    int ib = gridDim.x - 1 - blockIdx.x;     // heavy blocks first (128-row Q block)
    int h  = blockIdx.y;
    int tid = threadIdx.x, lane = tid & 31, warp = tid >> 5;
    int nkb = 2 * ib + 2;

    // ---- load Q tile (128 rows x 384B) ----
    const char* qg = (const char*)(Qsp + ((size_t)h * 32 + 2 * ib) * (64 * 192));
    #pragma unroll
    for (int l = 0; l < 12; l++) {
        int c = tid + l * 256;
        int row = c / 24, col = c - row * 24;
        cp16(qsmem + (uint32_t)(row * 400 + col * 16), qg + (size_t)row * 384 + col * 16);
    }
    asm volatile("cp.async.commit_group;" ::: "memory");

    auto load_kv = [&](int kb, int p) {
        uint32_t kdst = kvbase + (uint32_t)p * FLKV_B;
        uint32_t vdst = kdst + 192 * 72 * 2;
        const char* kg = (const char*)(Ksp + ((size_t)h * 32 + kb) * (192 * 64));
        const char* vg = (const char*)(Vsp + ((size_t)h * 32 + kb) * (192 * 64));
        #pragma unroll
        for (int l = 0; l < 6; l++) {
            int c = tid + l * 256;
            int row = c >> 3, col = c & 7;
            cp16(kdst + (uint32_t)(row * 144 + col * 16), kg + (size_t)row * 128 + col * 16);
            cp16(vdst + (uint32_t)(row * 144 + col * 16), vg + (size_t)row * 128 + col * 16);
        }
        asm volatile("cp.async.commit_group;" ::: "memory");
    };

    load_kv(0, 0);
    asm volatile("cp.async.wait_group 1;" ::: "memory");   // Q done
    __syncthreads();

    uint32_t qf[12][4];
    uint32_t qbase = qsmem + (uint32_t)(((warp * 16 + (lane & 15)) * 200 + (lane >> 4) * 8) * 2);
    #pragma unroll
    for (int s = 0; s < 12; s++)
        LDSM4(qf[s][0], qf[s][1], qf[s][2], qf[s][3], qbase + s * 32);

    uint32_t fragoff = (uint32_t)((lane & 15) * 144 + (lane >> 4) * 16);

    float O[8][4];
    float run_max[2] = {-1e30f, -1e30f};
    float run_sum[2] = {0.f, 0.f};
    #pragma unroll
    for (int nt = 0; nt < 8; nt++)
        #pragma unroll
        for (int e = 0; e < 4; e++) O[nt][e] = 0.f;

    for (int kb = 0; kb < nkb; kb++) {
        int p = kb & 1;
        __syncthreads();   // all warps done with buffer p^1 (previous compute)
        if (kb + 1 < nkb) {
            load_kv(kb + 1, p ^ 1);
            asm volatile("cp.async.wait_group 1;" ::: "memory");
        } else {
            asm volatile("cp.async.wait_group 0;" ::: "memory");
        }
        __syncthreads();   // kv(kb) visible

        uint32_t ksb = kvbase + (uint32_t)p * FLKV_B + fragoff;
        uint32_t vsb = ksb + 192 * 72 * 2;

        float S[8][4];
        #pragma unroll
        for (int nt = 0; nt < 8; nt++)
            #pragma unroll
            for (int e = 0; e < 4; e++) S[nt][e] = 0.f;
        #pragma unroll
        for (int s = 0; s < 12; s++) {
            uint32_t bfr[4][4];
            #pragma unroll
            for (int pq = 0; pq < 4; pq++)
                LDSM4T(bfr[pq][0], bfr[pq][1], bfr[pq][2], bfr[pq][3],
                       ksb + pq * 32 + s * (16 * 72 * 2));
            #pragma unroll
            for (int nt = 0; nt < 8; nt++) {
                uint32_t b0 = bfr[nt >> 1][(nt & 1) * 2];
                uint32_t b1 = bfr[nt >> 1][(nt & 1) * 2 + 1];
                mma_op<false>(S[nt], qf[s], b0, b1);
            }
        }

        // causal mask on the two diagonal-straddling blocks
        if (kb >= 2 * ib) {
            int off = 64 * kb - 128 * ib;   // 0 or 64
            #pragma unroll
            for (int nt = 0; nt < 8; nt++)
                #pragma unroll
                for (int e = 0; e < 4; e++) {
                    int rowl = warp * 16 + (lane >> 2) + (e >> 1) * 8;
                    int coll = nt * 8 + (lane & 3) * 2 + (e & 1) + off;
                    if (coll > rowl) S[nt][e] = -1e30f;
                }
        }

        float alpha[2];
        #pragma unroll
        for (int half = 0; half < 2; half++) {
            float m = -1e30f;
            #pragma unroll
            for (int nt = 0; nt < 8; nt++)
                m = fmaxf(m, fmaxf(S[nt][half * 2], S[nt][half * 2 + 1]));
            m = fmaxf(m, __shfl_xor_sync(0xffffffffu, m, 1));
            m = fmaxf(m, __shfl_xor_sync(0xffffffffu, m, 2));
            float nm = fmaxf(run_max[half], m);
            alpha[half] = __expf(run_max[half] - nm);
            run_max[half] = nm;
            float ps = 0.f;
            #pragma unroll
            for (int nt = 0; nt < 8; nt++) {
                float p0 = __expf(S[nt][half * 2]     - nm);
                float p1 = __expf(S[nt][half * 2 + 1] - nm);
                S[nt][half * 2]     = p0;
                S[nt][half * 2 + 1] = p1;
                ps += p0 + p1;
            }
            ps += __shfl_xor_sync(0xffffffffu, ps, 1);
            ps += __shfl_xor_sync(0xffffffffu, ps, 2);
            run_sum[half] = run_sum[half] * alpha[half] + ps;
        }
        #pragma unroll
        for (int nt = 0; nt < 8; nt++) {
            O[nt][0] *= alpha[0]; O[nt][1] *= alpha[0];
            O[nt][2] *= alpha[1]; O[nt][3] *= alpha[1];
        }

        uint32_t phi[4][4], plo[4][4];
        #pragma unroll
        for (int t = 0; t < 4; t++) {
            #pragma unroll
            for (int g = 0; g < 2; g++) {
                float c0 = S[2 * t + g][0], c1 = S[2 * t + g][1];
                float c2 = S[2 * t + g][2], c3 = S[2 * t + g][3];
                __nv_bfloat16 h0 = __float2bfloat16_rn(c0);
                __nv_bfloat16 h1 = __float2bfloat16_rn(c1);
                __nv_bfloat16 h2 = __float2bfloat16_rn(c2);
                __nv_bfloat16 h3 = __float2bfloat16_rn(c3);
                phi[t][g * 2 + 0] = ((uint32_t)*(unsigned short*)&h1 << 16) | *(unsigned short*)&h0;
                phi[t][g * 2 + 1] = ((uint32_t)*(unsigned short*)&h3 << 16) | *(unsigned short*)&h2;
                plo[t][g * 2 + 0] = pack_bf16(c0 - __bfloat162float(h0), c1 - __bfloat162float(h1));
                plo[t][g * 2 + 1] = pack_bf16(c2 - __bfloat162float(h2), c3 - __bfloat162float(h3));
            }
        }

        #pragma unroll
        for (int s = 0; s < 12; s++) {
            uint32_t bfr[4][4];
            #pragma unroll
            for (int pq = 0; pq < 4; pq++)
                LDSM4T(bfr[pq][0], bfr[pq][1], bfr[pq][2], bfr[pq][3],
                       vsb + pq * 32 + s * (16 * 72 * 2));
            const uint32_t* a = (s < 4) ? phi[s] : (s < 8) ? plo[s - 4] : phi[s - 8];
            #pragma unroll
            for (int nt = 0; nt < 8; nt++) {
                uint32_t b0 = bfr[nt >> 1][(nt & 1) * 2];
                uint32_t b1 = bfr[nt >> 1][(nt & 1) * 2 + 1];
                mma_op<false>(O[nt], a, b0, b1);
            }
        }
    }

    // ---- normalize + write fp16 2-term rows (stride 2*DIM) ----
    float inv0 = 1.0f / run_sum[0];
    float inv1 = 1.0f / run_sum[1];
    #pragma unroll
    for (int half = 0; half < 2; half++) {
        int row = ib * 128 + warp * 16 + (lane >> 2) + half * 8;
        size_t base = (size_t)row * (2 * DIM);
        float inv = half ? inv1 : inv0;
        #pragma unroll
        for (int nt = 0; nt < 8; nt++) {
            int col = h * DH + nt * 8 + (lane & 3) * 2;
            float v0 = O[nt][half * 2]     * inv;
            float v1 = O[nt][half * 2 + 1] * inv;
            __half h0 = __float2half_rn(v0);
            __half h1 = __float2half_rn(v1);
            __half l0 = __float2half_rn(v0 - __half2float(h0));
            __half l1 = __float2half_rn(v1 - __half2float(h1));
            __half2 hp = __halves2half2(h0, h1);
            __half2 lp = __halves2half2(l0, l1);
            *(__half2*)(ab + base + col)       = hp;
            *(__half2*)(ab + base + DIM + col) = lp;
        }
    }
}

// ---------------- launch ----------------
static inline void convw_f16_s(const float* src, __half* dst, long long K, long long N,
                               cudaStream_t st) {
    long long KN4 = K * N / 4;
    convw_f16_kernel<<<(unsigned)((KN4 + 255) / 256), 256, 0, st>>>((const float4*)src, dst, KN4);
}

#define BG_QKV   bgemm_kernel<2, true, false, false, false, 0>
#define BG_OUT   bgemm_kernel<2, true, false, true,  false, 0>
#define BG_FF1   bgemm_kernel<2, true, true,  false, true,  2>
#define BG_FF2   bgemm_kernel<2, true, true,  true,  false, 0>
#define BG_LOGIT bgemm_kernel<1, true, false, false, false, 0>

extern "C" void kernel_launch(void* const* d_in, const int* in_sizes, int n_in,
                              void* d_out, int out_size) {
    const int*   tokens      = (const int*)  d_in[0];
    const float* emb         = (const float*)d_in[1];
    const float* gamma_attn  = (const float*)d_in[2];
    const float* w_qkv       = (const float*)d_in[3];
    const float* w_out       = (const float*)d_in[4];
    const float* gamma_ff    = (const float*)d_in[5];
    const float* w_ff1       = (const float*)d_in[6];
    const float* b_ff1       = (const float*)d_in[7];
    const float* w_ff2       = (const float*)d_in[8];
    const float* b_ff2       = (const float*)d_in[9];
    const float* gamma_final = (const float*)d_in[10];
    const float* w_logits    = (const float*)d_in[11];
    float* out = (float*)d_out;

    float *x, *qkv;
    __nv_bfloat16 *ab, *ab2, *wb, *qs, *ks, *vs;
    cudaGetSymbolAddress((void**)&x,   g_x);
    cudaGetSymbolAddress((void**)&qkv, g_qkv);
    cudaGetSymbolAddress((void**)&ab,  g_ab);
    cudaGetSymbolAddress((void**)&ab2, g_ab2);
    cudaGetSymbolAddress((void**)&wb,  g_wb);
    cudaGetSymbolAddress((void**)&qs,  g_qs);
    cudaGetSymbolAddress((void**)&ks,  g_ks);
    cudaGetSymbolAddress((void**)&vs,  g_vs);

    cudaFuncSetAttribute(flash_kernel, cudaFuncAttributeMaxDynamicSharedMemorySize, FL_SMEM);
    cudaFuncSetAttribute(BG_QKV,   cudaFuncAttributeMaxDynamicSharedMemorySize, GEMM_SMEM);
    cudaFuncSetAttribute(BG_OUT,   cudaFuncAttributeMaxDynamicSharedMemorySize, GEMM_SMEM);
    cudaFuncSetAttribute(BG_FF1,   cudaFuncAttributeMaxDynamicSharedMemorySize, GEMM_SMEM);
    cudaFuncSetAttribute(BG_FF2,   cudaFuncAttributeMaxDynamicSharedMemorySize, GEMM_SMEM);
    cudaFuncSetAttribute(BG_LOGIT, cudaFuncAttributeMaxDynamicSharedMemorySize, GEMM_SMEM);

    // lazily-created side stream + events
    static cudaStream_t s2 = nullptr;
    static cudaEvent_t evFork;
    static cudaEvent_t evW[17];
    if (!s2) {
        cudaStreamCreateWithFlags(&s2, cudaStreamNonBlocking);
        cudaEventCreateWithFlags(&evFork, cudaEventDisableTiming);
        for (int i = 0; i < 17; i++)
            cudaEventCreateWithFlags(&evW[i], cudaEventDisableTiming);
    }

    // fork: weight conversions on s2
    cudaEventRecord(evFork, 0);
    cudaStreamWaitEvent(s2, evFork, 0);
    for (int l = 0; l < DEPTH; l++) {
        convw_f16_s(w_qkv + (size_t)l * DIM * 3 * DIM, (__half*)(wb + WB_QKV(l)), DIM, 3 * DIM, s2);
        cudaEventRecord(evW[4 * l + 0], s2);
        convw_f16_s(w_out + (size_t)l * DIM * DIM, (__half*)(wb + WB_OUT(l)), DIM, DIM, s2);
        cudaEventRecord(evW[4 * l + 1], s2);
        convw_f16_s(w_ff1 + (size_t)l * DIM * FFD, (__half*)(wb + WB_FF1(l)), DIM, FFD, s2);
        cudaEventRecord(evW[4 * l + 2], s2);
        convw_f16_s(w_ff2 + (size_t)l * FFD * DIM, (__half*)(wb + WB_FF2(l)), FFD, DIM, s2);
        cudaEventRecord(evW[4 * l + 3], s2);
    }
    convw_f16_s(w_logits, (__half*)(wb + WB_LOGITS), DIM, VOCAB, s2);
    cudaEventRecord(evW[16], s2);

    // main chain
    embed_kernel<<<SEQ * DIM / 256, 256>>>(tokens, emb, x);

    for (int l = 0; l < DEPTH; l++) {
        rmsnorm_split_f16_kernel<<<SEQ, 256>>>(x, gamma_attn + l * DIM, (__half*)ab);
        cudaStreamWaitEvent(0, evW[4 * l + 0], 0);
        BG_QKV<<<dim3(SEQ / 128, 3 * DIM / 128), 256, GEMM_SMEM>>>(
            ab, wb + WB_QKV(l), nullptr, qkv, nullptr, 3 * DIM, DIM / 64);
        qsplit_kernel<<<dim3(32, HEADS), 256>>>(qkv, qs);
        kvsplit_kernel<<<dim3(32, HEADS), 256>>>(qkv, ks, vs);
        flash_kernel<<<dim3(SEQ / 128, HEADS), 256, FL_SMEM>>>(qs, ks, vs, (__half*)ab);
        cudaStreamWaitEvent(0, evW[4 * l + 1], 0);
        BG_OUT<<<dim3(SEQ / 128, DIM / 128), 256, GEMM_SMEM>>>(
            ab, wb + WB_OUT(l), nullptr, x, nullptr, DIM, DIM / 64);
        // --- feedforward block ---
        rmsnorm_split_f16_kernel<<<SEQ, 256>>>(x, gamma_ff + l * DIM, (__half*)ab);
        cudaStreamWaitEvent(0, evW[4 * l + 2], 0);
        BG_FF1<<<dim3(SEQ / 128, FFD / 128), 256, GEMM_SMEM>>>(
            ab, wb + WB_FF1(l), b_ff1 + (size_t)l * FFD, nullptr, ab2, FFD, DIM / 64);
        cudaStreamWaitEvent(0, evW[4 * l + 3], 0);
        BG_FF2<<<dim3(SEQ / 128, DIM / 128), 256, GEMM_SMEM>>>(
            ab2, wb + WB_FF2(l), b_ff2 + (size_t)l * DIM, x, nullptr, DIM, FFD / 64);
    }

    // final norm + fp16 1-term logits GEMM
    rmsnorm_f16_kernel<<<SEQ, 256>>>(x, gamma_final, (__half*)ab);
    cudaStreamWaitEvent(0, evW[16], 0);
    BG_LOGIT<<<dim3(SEQ / 128, VOCAB / 128), 256, GEMM_SMEM>>>(
        ab, wb + WB_LOGITS, nullptr, out, nullptr, VOCAB, DIM / 64);
}

// round 14
// speedup vs baseline: 1.0338x; 1.0338x over previous
#include <cuda_runtime.h>
#include <cuda_bf16.h>
#include <cuda_fp16.h>
#include <math.h>
#include <float.h>
#include <stdint.h>

// ---------------- problem constants ----------------
#define SEQ   2048
#define DIM   1024
#define DEPTH 4
#define HEADS 16
#define DH    64
#define FFD   4096
#define VOCAB 32000

// ---------------- scratch (static device globals) ----------------
__device__ float g_x   [SEQ * DIM];
__device__ float g_qkv [SEQ * 3 * DIM];
__device__ __nv_bfloat16 g_ab [SEQ * 3 * DIM];
__device__ __nv_bfloat16 g_ab2[SEQ * 3 * FFD];
__device__ __nv_bfloat16 g_wb [133431296ull];
__device__ __align__(16) __nv_bfloat16 g_qs[6291456ull];  // Q tiles [h][ib][64][192]
__device__ __align__(16) __nv_bfloat16 g_ks[6291456ull];  // K tiles [h][jb][192][64]
__device__ __align__(16) __nv_bfloat16 g_vs[6291456ull];  // V tiles [h][jb][192][64]

// weight offsets in g_wb (2-byte elements) — all fp16 hi-only
#define WB_QKV(l)  ((size_t)(l) * 6291456ull)
#define WB_OUT(l)  (25165824ull + (size_t)(l) * 2097152ull)
#define WB_FF1(l)  (33554432ull + (size_t)(l) * 8388608ull)
#define WB_FF2(l)  (67108864ull + (size_t)(l) * 8388608ull)
#define WB_LOGITS  100663296ull

// ---------------- helpers ----------------
__device__ __forceinline__ uint32_t smem_u32(const void* p) {
    return (uint32_t)__cvta_generic_to_shared(p);
}
__device__ __forceinline__ void cp16(uint32_t s, const void* g) {
    asm volatile("cp.async.cg.shared.global [%0], [%1], 16;" :: "r"(s), "l"(g));
}
__device__ __forceinline__ uint32_t pack_bf16(float a, float b) {
    __nv_bfloat162 t = __floats2bfloat162_rn(a, b);
    return *(uint32_t*)&t;
}

// ---------------- weight conv fp16 (hi only) ----------------
__global__ void __launch_bounds__(256) convw_f16_kernel(const float4* __restrict__ w,
                                                        __half* __restrict__ o,
                                                        long long KN4) {
    long long idx = (long long)blockIdx.x * 256 + threadIdx.x;
    if (idx >= KN4) return;
    float4 v = w[idx];
    union { __half u[4]; uint2 p; } h4;
    h4.u[0] = __float2half_rn(v.x); h4.u[1] = __float2half_rn(v.y);
    h4.u[2] = __float2half_rn(v.z); h4.u[3] = __float2half_rn(v.w);
    *(uint2*)(o + 4 * idx) = h4.p;
}

// ---------------- embed ----------------
__global__ void __launch_bounds__(256) embed_kernel(const int* __restrict__ tokens,
                                                    const float* __restrict__ emb,
                                                    float* __restrict__ x) {
    int idx = blockIdx.x * 256 + threadIdx.x;
    int row = idx >> 10;
    int d   = idx & 1023;
    x[idx] = emb[(size_t)tokens[row] * DIM + d];
}

// ---------------- rmsnorm + split fp16 2-term: A' = [hi | lo] ----
__global__ void __launch_bounds__(256) rmsnorm_split_f16_kernel(const float* __restrict__ x,
                                                                const float* __restrict__ gamma,
                                                                __half* __restrict__ ab) {
    int row = blockIdx.x;
    const float* xr = x + (size_t)row * DIM;
    float ss = 0.f;
    for (int i = threadIdx.x; i < DIM; i += 256) { float v = xr[i]; ss += v * v; }
    __shared__ float red[256];
    red[threadIdx.x] = ss;
    __syncthreads();
    for (int s = 128; s > 0; s >>= 1) {
        if (threadIdx.x < s) red[threadIdx.x] += red[threadIdx.x + s];
        __syncthreads();
    }
    float scale = 32.0f / fmaxf(sqrtf(red[0]), 1e-12f);
    __half* ar = ab + (size_t)row * (2 * DIM);
    for (int i = threadIdx.x; i < DIM; i += 256) {
        float v = xr[i] * scale * gamma[i];
        __half hi = __float2half_rn(v);
        __half lo = __float2half_rn(v - __half2float(hi));
        ar[i] = hi;
        ar[DIM + i] = lo;
    }
}

// ---------------- rmsnorm fp16 1-term (logits A) ----------------
__global__ void __launch_bounds__(256) rmsnorm_f16_kernel(const float* __restrict__ x,
                                                          const float* __restrict__ gamma,
                                                          __half* __restrict__ ab) {
    int row = blockIdx.x;
    const float* xr = x + (size_t)row * DIM;
    float ss = 0.f;
    for (int i = threadIdx.x; i < DIM; i += 256) { float v = xr[i]; ss += v * v; }
    __shared__ float red[256];
    red[threadIdx.x] = ss;
    __syncthreads();
    for (int s = 128; s > 0; s >>= 1) {
        if (threadIdx.x < s) red[threadIdx.x] += red[threadIdx.x + s];
        __syncthreads();
    }
    float scale = 32.0f / fmaxf(sqrtf(red[0]), 1e-12f);
    __half* ar = ab + (size_t)row * DIM;
    for (int i = threadIdx.x; i < DIM; i += 256)
        ar[i] = __float2half_rn(xr[i] * scale * gamma[i]);
}

// ---------------- Q split (rotary fused, scaled): -> [h][ib][64][192] ----------------
#define L2_10000 13.287712379549449f
__global__ void __launch_bounds__(256) qsplit_kernel(const float* __restrict__ qkv,
                                                     __nv_bfloat16* __restrict__ Qsp) {
    int ib = blockIdx.x, h = blockIdx.y;
    int tid = threadIdx.x;
    __nv_bfloat16* qt = Qsp + ((size_t)h * 32 + ib) * (64 * 192);
    #pragma unroll
    for (int l = 0; l < 16; l++) {
        int e = tid + l * 256;
        int i = e >> 6, d = e & 63;
        int pos = ib * 64 + i;
        const float* qrow = qkv + (size_t)pos * (3 * DIM) + h * DH;
        float x = qrow[d];
        float other = qrow[d ^ 32];
        int j = d & 31;
        float inv = exp2f((float)j * (-L2_10000 / 32.0f));
        float fr = (float)pos * inv;
        float c, s;
        sincosf(fr, &s, &c);
        float val = ((d < 32) ? (x * c - other * s) : (x * c + other * s)) * 0.125f;
        __nv_bfloat16 hi = __float2bfloat16_rn(val);
        __nv_bfloat16 lo = __float2bfloat16_rn(val - __bfloat162float(hi));
        qt[(size_t)i * 192 + d]       = hi;
        qt[(size_t)i * 192 + 64 + d]  = lo;
        qt[(size_t)i * 192 + 128 + d] = hi;
    }
}

// ---------------- K/V split (K rotary fused, K transposed): -> [h][jb][192][64] ------
__global__ void __launch_bounds__(256) kvsplit_kernel(const float* __restrict__ qkv,
                                                      __nv_bfloat16* __restrict__ Ksp,
                                                      __nv_bfloat16* __restrict__ Vsp) {
    __shared__ float kt_s[64][65];
    int jb = blockIdx.x, h = blockIdx.y;
    int tid = threadIdx.x;
    __nv_bfloat16* kt = Ksp + ((size_t)h * 32 + jb) * (192 * 64);
    __nv_bfloat16* vt = Vsp + ((size_t)h * 32 + jb) * (192 * 64);
    #pragma unroll
    for (int l = 0; l < 16; l++) {
        int e = tid + l * 256;
        int j = e >> 6, d = e & 63;
        int pos = jb * 64 + j;
        const float* krow = qkv + (size_t)pos * (3 * DIM) + (HEADS + h) * DH;
        float x = krow[d];
        float other = krow[d ^ 32];
        int jj = d & 31;
        float inv = exp2f((float)jj * (-L2_10000 / 32.0f));
        float fr = (float)pos * inv;
        float c, s;
        sincosf(fr, &s, &c);
        kt_s[d][j] = (d < 32) ? (x * c - other * s) : (x * c + other * s);
        const float* vrow = qkv + (size_t)pos * (3 * DIM) + (2 * HEADS + h) * DH;
        float v = vrow[d];
        __nv_bfloat16 vh = __float2bfloat16_rn(v);
        __nv_bfloat16 vl = __float2bfloat16_rn(v - __bfloat162float(vh));
        vt[(size_t)j * 64 + d]         = vh;
        vt[(size_t)(64 + j) * 64 + d]  = vh;
        vt[(size_t)(128 + j) * 64 + d] = vl;
    }
    __syncthreads();
    #pragma unroll
    for (int l = 0; l < 16; l++) {
        int e = tid + l * 256;
        int d = e >> 6, j = e & 63;
        float val = kt_s[d][j];
        __nv_bfloat16 hi = __float2bfloat16_rn(val);
        __nv_bfloat16 lo = __float2bfloat16_rn(val - __bfloat162float(hi));
        kt[(size_t)d * 64 + j]         = hi;
        kt[(size_t)(64 + d) * 64 + j]  = hi;
        kt[(size_t)(128 + d) * 64 + j] = lo;
    }
}

// ---------------- mma primitives ----------------
#define LDSM4(R0,R1,R2,R3,addr) \
    asm volatile("ldmatrix.sync.aligned.m8n8.x4.shared.b16 {%0,%1,%2,%3},[%4];" \
        : "=r"(R0),"=r"(R1),"=r"(R2),"=r"(R3) : "r"(addr))
#define LDSM4T(R0,R1,R2,R3,addr) \
    asm volatile("ldmatrix.sync.aligned.m8n8.x4.trans.shared.b16 {%0,%1,%2,%3},[%4];" \
        : "=r"(R0),"=r"(R1),"=r"(R2),"=r"(R3) : "r"(addr))

template<bool F16>
__device__ __forceinline__ void mma_op(float* d, const uint32_t* a, uint32_t b0, uint32_t b1) {
    if (F16)
        asm volatile("mma.sync.aligned.m16n8k16.row.col.f32.f16.f16.f32 "
            "{%0,%1,%2,%3},{%4,%5,%6,%7},{%8,%9},{%0,%1,%2,%3};"
            : "+f"(d[0]),"+f"(d[1]),"+f"(d[2]),"+f"(d[3])
            : "r"(a[0]),"r"(a[1]),"r"(a[2]),"r"(a[3]),"r"(b0),"r"(b1));
    else
        asm volatile("mma.sync.aligned.m16n8k16.row.col.f32.bf16.bf16.f32 "
            "{%0,%1,%2,%3},{%4,%5,%6,%7},{%8,%9},{%0,%1,%2,%3};"
            : "+f"(d[0]),"+f"(d[1]),"+f"(d[2]),"+f"(d[3])
            : "r"(a[0]),"r"(a[1]),"r"(a[2]),"r"(a[3]),"r"(b0),"r"(b1));
}

// ---------------- tensor-core GEMM (K-chunk 64, 3 stages, frag dbuf) ----
// SPLITM: 0 = fp32 C (optional RES), 2 = fp16 2-term A'-format
#define A_STG_B 18432
#define B_STG_B 17408
#define SSTG_B  (A_STG_B + B_STG_B)
#define GEMM_SMEM (3 * SSTG_B)

template<int TERMS, bool F16, bool BIAS, bool RES, bool GELU, int SPLITM>
__global__ void __launch_bounds__(256, 2)
bgemm_kernel(const __nv_bfloat16* __restrict__ A,
             const __nv_bfloat16* __restrict__ B,
             const float* __restrict__ bias,
             float* __restrict__ C,
             __nv_bfloat16* __restrict__ Cs,
             int N, int Ku64)
{
    extern __shared__ __align__(16) __nv_bfloat16 sm[];
    uint32_t sbase = smem_u32(sm);

    int tid  = threadIdx.x;
    int lane = tid & 31;
    int warp = tid >> 5;
    int wm = warp >> 2;
    int wn = warp & 3;
    int bm = blockIdx.x * 128;
    int bn = blockIdx.y * 128;
    int Astride = TERMS * Ku64 * 64;

    const char* gAbase = (const char*)(A + (size_t)bm * Astride);
    const char* gBbase = (const char*)(B + bn);

    uint32_t aFrag = (uint32_t)(((wm * 64 + (lane & 15)) * 72 + (lane >> 4) * 8) * 2);
    uint32_t bFrag = (uint32_t)(A_STG_B + ((lane & 15) * 136 + wn * 32 + (lane >> 4) * 8) * 2);

    float acc[4][4][4];
    #pragma unroll
    for (int i = 0; i < 4; i++)
        #pragma unroll
        for (int j = 0; j < 4; j++)
            #pragma unroll
            for (int k = 0; k < 4; k++) acc[i][j][k] = 0.f;

    int steps = TERMS * Ku64;

    auto load_stage = [&](int t) {
        uint32_t so = sbase + (uint32_t)(t % 3) * SSTG_B;
        int bs = (t < Ku64) ? t : t - Ku64;
        const char* aP = gAbase + (size_t)t * 128;
        const char* bP = gBbase + (size_t)bs * ((size_t)N * 128);
        #pragma unroll
        for (int j = 0; j < 4; j++) {
            int i = tid + j * 256;
            cp16(so + (uint32_t)(((i >> 3) * 72 + (i & 7) * 8) * 2),
                 aP + (size_t)(i >> 3) * Astride * 2 + (i & 7) * 16);
            cp16(so + (uint32_t)(A_STG_B + ((i >> 4) * 136 + (i & 15) * 8) * 2),
                 bP + (size_t)(i >> 4) * N * 2 + (i & 15) * 16);
        }
        asm volatile("cp.async.commit_group;" ::: "memory");
    };

    load_stage(0);
    load_stage(1);

    uint32_t af[2][16], bf[2][8];

    auto ldsA = [&](uint32_t* f, uint32_t stg, int kk) {
        #pragma unroll
        for (int mt = 0; mt < 4; mt++) {
            uint32_t addr = stg + aFrag + mt * (16 * 72 * 2) + kk * 32;
            LDSM4(f[mt * 4 + 0], f[mt * 4 + 1], f[mt * 4 + 2], f[mt * 4 + 3], addr);
        }
    };
    auto ldsB = [&](uint32_t* f, uint32_t stg, int kk) {
        #pragma unroll
        for (int p = 0; p < 2; p++) {
            uint32_t addr = stg + bFrag + p * 32 + kk * (16 * 136 * 2);
            LDSM4T(f[p * 4 + 0], f[p * 4 + 1], f[p * 4 + 2], f[p * 4 + 3], addr);
        }
    };

    for (int t = 0; t < steps; t++) {
        if (t + 1 < steps) asm volatile("cp.async.wait_group 1;" ::: "memory");
        else               asm volatile("cp.async.wait_group 0;" ::: "memory");
        __syncthreads();
        if (t + 2 < steps) load_stage(t + 2);

        uint32_t stg = sbase + (uint32_t)(t % 3) * SSTG_B;
        ldsA(af[0], stg, 0);
        ldsB(bf[0], stg, 0);
        #pragma unroll
        for (int kk = 0; kk < 4; kk++) {
            int cur = kk & 1, nxt = cur ^ 1;
            if (kk < 3) { ldsA(af[nxt], stg, kk + 1); ldsB(bf[nxt], stg, kk + 1); }
            #pragma unroll
            for (int mt = 0; mt < 4; mt++) {
                #pragma unroll
                for (int nt = 0; nt < 4; nt++) {
                    uint32_t b0 = bf[cur][(nt >> 1) * 4 + (nt & 1) * 2];
                    uint32_t b1 = bf[cur][(nt >> 1) * 4 + (nt & 1) * 2 + 1];
                    mma_op<F16>(acc[mt][nt], &af[cur][mt * 4], b0, b1);
                }
            }
        }
    }

    int row0 = bm + wm * 64;
    int col0 = bn + wn * 32;
    #pragma unroll
    for (int mt = 0; mt < 4; mt++) {
        #pragma unroll
        for (int nt = 0; nt < 4; nt++) {
            int r = row0 + mt * 16 + (lane >> 2);
            int c = col0 + nt * 8 + (lane & 3) * 2;
            #pragma unroll
            for (int half = 0; half < 2; half++) {
                int rr = r + half * 8;
                #pragma unroll
                for (int e = 0; e < 2; e++) {
                    float val = acc[mt][nt][half * 2 + e];
                    int cc = c + e;
                    if (BIAS) val += bias[cc];
                    if (GELU) val = 0.5f * val * (1.0f + erff(val * 0.70710678118654752f));
                    if (SPLITM == 2) {
                        __half* Ch = (__half*)Cs;
                        __half hi = __float2half_rn(val);
                        __half lo = __float2half_rn(val - __half2float(hi));
                        size_t base = (size_t)rr * (2 * (size_t)N);
                        Ch[base + cc] = hi;
                        Ch[base + N + cc] = lo;
                    } else {
                        size_t off = (size_t)rr * N + cc;
                        if (RES) val += C[off];
                        C[off] = val;
                    }
                }
            }
        }
    }
}

// ---------------- tensor-core flash attention (R12 geometry, fp16 2-term output) -----
// grid (SEQ/64, HEADS), 128 threads (4 warps x 16 Q-rows), 2 CTA/SM.
#define FL_SMEM ((64 * 200 + 192 * 72 + 192 * 72) * 2)

__global__ void __launch_bounds__(128) flash_kernel(const __nv_bfloat16* __restrict__ Qsp,
                                                    const __nv_bfloat16* __restrict__ Ksp,
                                                    const __nv_bfloat16* __restrict__ Vsp,
                                                    __half* __restrict__ ab) {
    extern __shared__ __align__(16) __nv_bfloat16 fsm[];
    __nv_bfloat16* Qs = fsm;                 // [64][200]
    __nv_bfloat16* Ks = Qs + 64 * 200;       // [192][72]
    __nv_bfloat16* Vs = Ks + 192 * 72;       // [192][72]

    int br = gridDim.x - 1 - blockIdx.x;     // heavy blocks first
    int h  = blockIdx.y;
    int tid = threadIdx.x, lane = tid & 31, warp = tid >> 5;

    uint32_t qsmem = smem_u32(Qs);
    uint32_t ksmem = smem_u32(Ks);
    uint32_t vsmem = smem_u32(Vs);

    const char* qg = (const char*)(Qsp + ((size_t)h * 32 + br) * (64 * 192));
    #pragma unroll
    for (int l = 0; l < 12; l++) {
        int c = tid + l * 128;
        int row = c / 24, col = c - row * 24;
        cp16(qsmem + (uint32_t)(row * 400 + col * 16), qg + (size_t)row * 384 + col * 16);
    }
    asm volatile("cp.async.commit_group;" ::: "memory");
    asm volatile("cp.async.wait_group 0;" ::: "memory");
    __syncthreads();

    uint32_t qf[12][4];
    uint32_t qbase = qsmem + (uint32_t)(((warp * 16 + (lane & 15)) * 200 + (lane >> 4) * 8) * 2);
    #pragma unroll
    for (int s = 0; s < 12; s++)
        LDSM4(qf[s][0], qf[s][1], qf[s][2], qf[s][3], qbase + s * 32);

    uint32_t ksb = ksmem + (uint32_t)(((lane & 15) * 72 + (lane >> 4) * 8) * 2);
    uint32_t vsb = vsmem + (uint32_t)(((lane & 15) * 72 + (lane >> 4) * 8) * 2);

    float O[8][4];
    float run_max[2] = {-1e30f, -1e30f};
    float run_sum[2] = {0.f, 0.f};
    #pragma unroll
    for (int nt = 0; nt < 8; nt++)
        #pragma unroll
        for (int e = 0; e < 4; e++) O[nt][e] = 0.f;

    for (int kb = 0; kb <= br; kb++) {
        __syncthreads();
        const char* kg = (const char*)(Ksp + ((size_t)h * 32 + kb) * (192 * 64));
        const char* vg = (const char*)(Vsp + ((size_t)h * 32 + kb) * (192 * 64));
        #pragma unroll
        for (int l = 0; l < 12; l++) {
            int c = tid + l * 128;
            int row = c >> 3, col = c & 7;
            cp16(ksmem + (uint32_t)(row * 144 + col * 16), kg + (size_t)row * 128 + col * 16);
            cp16(vsmem + (uint32_t)(row * 144 + col * 16), vg + (size_t)row * 128 + col * 16);
        }
        asm volatile("cp.async.commit_group;" ::: "memory");
        asm volatile("cp.async.wait_group 0;" ::: "memory");
        __syncthreads();

        float S[8][4];
        #pragma unroll
        for (int nt = 0; nt < 8; nt++)
            #pragma unroll
            for (int e = 0; e < 4; e++) S[nt][e] = 0.f;
        #pragma unroll
        for (int s = 0; s < 12; s++) {
            uint32_t bfr[4][4];
            #pragma unroll
            for (int p = 0; p < 4; p++)
                LDSM4T(bfr[p][0], bfr[p][1], bfr[p][2], bfr[p][3],
                       ksb + p * 32 + s * (16 * 72 * 2));
            #pragma unroll
            for (int nt = 0; nt < 8; nt++) {
                uint32_t b0 = bfr[nt >> 1][(nt & 1) * 2];
                uint32_t b1 = bfr[nt >> 1][(nt & 1) * 2 + 1];
                mma_op<false>(S[nt], qf[s], b0, b1);
            }
        }

        if (kb == br) {
            #pragma unroll
            for (int nt = 0; nt < 8; nt++)
                #pragma unroll
                for (int e = 0; e < 4; e++) {
                    int rowl = warp * 16 + (lane >> 2) + (e >> 1) * 8;
                    int coll = nt * 8 + (lane & 3) * 2 + (e & 1);
                    if (coll > rowl) S[nt][e] = -1e30f;
                }
        }

        float alpha[2];
        #pragma unroll
        for (int half = 0; half < 2; half++) {
            float m = -1e30f;
            #pragma unroll
            for (int nt = 0; nt < 8; nt++)
                m = fmaxf(m, fmaxf(S[nt][half * 2], S[nt][half * 2 + 1]));
            m = fmaxf(m, __shfl_xor_sync(0xffffffffu, m, 1));
            m = fmaxf(m, __shfl_xor_sync(0xffffffffu, m, 2));
            float nm = fmaxf(run_max[half], m);
            alpha[half] = __expf(run_max[half] - nm);
            run_max[half] = nm;
            float ps = 0.f;
            #pragma unroll
            for (int nt = 0; nt < 8; nt++) {
                float p0 = __expf(S[nt][half * 2]     - nm);
                float p1 = __expf(S[nt][half * 2 + 1] - nm);
                S[nt][half * 2]     = p0;
                S[nt][half * 2 + 1] = p1;
                ps += p0 + p1;
            }
            ps += __shfl_xor_sync(0xffffffffu, ps, 1);
            ps += __shfl_xor_sync(0xffffffffu, ps, 2);
            run_sum[half] = run_sum[half] * alpha[half] + ps;
        }
        #pragma unroll
        for (int nt = 0; nt < 8; nt++) {
            O[nt][0] *= alpha[0]; O[nt][1] *= alpha[0];
            O[nt][2] *= alpha[1]; O[nt][3] *= alpha[1];
        }

        uint32_t phi[4][4], plo[4][4];
        #pragma unroll
        for (int t = 0; t < 4; t++) {
            #pragma unroll
            for (int g = 0; g < 2; g++) {
                float c0 = S[2 * t + g][0], c1 = S[2 * t + g][1];
                float c2 = S[2 * t + g][2], c3 = S[2 * t + g][3];
                __nv_bfloat16 h0 = __float2bfloat16_rn(c0);
                __nv_bfloat16 h1 = __float2bfloat16_rn(c1);
                __nv_bfloat16 h2 = __float2bfloat16_rn(c2);
                __nv_bfloat16 h3 = __float2bfloat16_rn(c3);
                phi[t][g * 2 + 0] = ((uint32_t)*(unsigned short*)&h1 << 16) | *(unsigned short*)&h0;
                phi[t][g * 2 + 1] = ((uint32_t)*(unsigned short*)&h3 << 16) | *(unsigned short*)&h2;
                plo[t][g * 2 + 0] = pack_bf16(c0 - __bfloat162float(h0), c1 - __bfloat162float(h1));
                plo[t][g * 2 + 1] = pack_bf16(c2 - __bfloat162float(h2), c3 - __bfloat162float(h3));
            }
        }

        #pragma unroll
        for (int s = 0; s < 12; s++) {
            uint32_t bfr[4][4];
            #pragma unroll
            for (int p = 0; p < 4; p++)
                LDSM4T(bfr[p][0], bfr[p][1], bfr[p][2], bfr[p][3],
                       vsb + p * 32 + s * (16 * 72 * 2));
            const uint32_t* a = (s < 4) ? phi[s] : (s < 8) ? plo[s - 4] : phi[s - 8];
            #pragma unroll
            for (int nt = 0; nt < 8; nt++) {
                uint32_t b0 = bfr[nt >> 1][(nt & 1) * 2];
                uint32_t b1 = bfr[nt >> 1][(nt & 1) * 2 + 1];
                mma_op<false>(O[nt], a, b0, b1);
            }
        }
    }

    // ---- normalize + write fp16 2-term rows (stride 2*DIM) ----
    float inv0 = 1.0f / run_sum[0];
    float inv1 = 1.0f / run_sum[1];
    #pragma unroll
    for (int half = 0; half < 2; half++) {
        int row = br * 64 + warp * 16 + (lane >> 2) + half * 8;
        size_t base = (size_t)row * (2 * DIM);
        float inv = half ? inv1 : inv0;
        #pragma unroll
        for (int nt = 0; nt < 8; nt++) {
            int col = h * DH + nt * 8 + (lane & 3) * 2;
            float v0 = O[nt][half * 2]     * inv;
            float v1 = O[nt][half * 2 + 1] * inv;
            __half h0 = __float2half_rn(v0);
            __half h1 = __float2half_rn(v1);
            __half l0 = __float2half_rn(v0 - __half2float(h0));
            __half l1 = __float2half_rn(v1 - __half2float(h1));
            *(__half2*)(ab + base + col)       = __halves2half2(h0, h1);
            *(__half2*)(ab + base + DIM + col) = __halves2half2(l0, l1);
        }
    }
}

// ---------------- launch ----------------
static inline void convw_f16_s(const float* src, __half* dst, long long K, long long N,
                               cudaStream_t st) {
    long long KN4 = K * N / 4;
    convw_f16_kernel<<<(unsigned)((KN4 + 255) / 256), 256, 0, st>>>((const float4*)src, dst, KN4);
}

#define BG_QKV   bgemm_kernel<2, true, false, false, false, 0>
#define BG_OUT   bgemm_kernel<2, true, false, true,  false, 0>
#define BG_FF1   bgemm_kernel<2, true, true,  false, true,  2>
#define BG_FF2   bgemm_kernel<2, true, true,  true,  false, 0>
#define BG_LOGIT bgemm_kernel<1, true, false, false, false, 0>

extern "C" void kernel_launch(void* const* d_in, const int* in_sizes, int n_in,
                              void* d_out, int out_size) {
    const int*   tokens      = (const int*)  d_in[0];
    const float* emb         = (const float*)d_in[1];
    const float* gamma_attn  = (const float*)d_in[2];
    const float* w_qkv       = (const float*)d_in[3];
    const float* w_out       = (const float*)d_in[4];
    const float* gamma_ff    = (const float*)d_in[5];
    const float* w_ff1       = (const float*)d_in[6];
    const float* b_ff1       = (const float*)d_in[7];
    const float* w_ff2       = (const float*)d_in[8];
    const float* b_ff2       = (const float*)d_in[9];
    const float* gamma_final = (const float*)d_in[10];
    const float* w_logits    = (const float*)d_in[11];
    float* out = (float*)d_out;

    float *x, *qkv;
    __nv_bfloat16 *ab, *ab2, *wb, *qs, *ks, *vs;
    cudaGetSymbolAddress((void**)&x,   g_x);
    cudaGetSymbolAddress((void**)&qkv, g_qkv);
    cudaGetSymbolAddress((void**)&ab,  g_ab);
    cudaGetSymbolAddress((void**)&ab2, g_ab2);
    cudaGetSymbolAddress((void**)&wb,  g_wb);
    cudaGetSymbolAddress((void**)&qs,  g_qs);
    cudaGetSymbolAddress((void**)&ks,  g_ks);
    cudaGetSymbolAddress((void**)&vs,  g_vs);

    cudaFuncSetAttribute(flash_kernel, cudaFuncAttributeMaxDynamicSharedMemorySize, FL_SMEM);
    cudaFuncSetAttribute(BG_QKV,   cudaFuncAttributeMaxDynamicSharedMemorySize, GEMM_SMEM);
    cudaFuncSetAttribute(BG_OUT,   cudaFuncAttributeMaxDynamicSharedMemorySize, GEMM_SMEM);
    cudaFuncSetAttribute(BG_FF1,   cudaFuncAttributeMaxDynamicSharedMemorySize, GEMM_SMEM);
    cudaFuncSetAttribute(BG_FF2,   cudaFuncAttributeMaxDynamicSharedMemorySize, GEMM_SMEM);
    cudaFuncSetAttribute(BG_LOGIT, cudaFuncAttributeMaxDynamicSharedMemorySize, GEMM_SMEM);

    // lazily-created side stream + events
    static cudaStream_t s2 = nullptr;
    static cudaEvent_t evFork;
    static cudaEvent_t evW[17];
    if (!s2) {
        cudaStreamCreateWithFlags(&s2, cudaStreamNonBlocking);
        cudaEventCreateWithFlags(&evFork, cudaEventDisableTiming);
        for (int i = 0; i < 17; i++)
            cudaEventCreateWithFlags(&evW[i], cudaEventDisableTiming);
    }

    // fork: weight conversions on s2
    cudaEventRecord(evFork, 0);
    cudaStreamWaitEvent(s2, evFork, 0);
    for (int l = 0; l < DEPTH; l++) {
        convw_f16_s(w_qkv + (size_t)l * DIM * 3 * DIM, (__half*)(wb + WB_QKV(l)), DIM, 3 * DIM, s2);
        cudaEventRecord(evW[4 * l + 0], s2);
        convw_f16_s(w_out + (size_t)l * DIM * DIM, (__half*)(wb + WB_OUT(l)), DIM, DIM, s2);
        cudaEventRecord(evW[4 * l + 1], s2);
        convw_f16_s(w_ff1 + (size_t)l * DIM * FFD, (__half*)(wb + WB_FF1(l)), DIM, FFD, s2);
        cudaEventRecord(evW[4 * l + 2], s2);
        convw_f16_s(w_ff2 + (size_t)l * FFD * DIM, (__half*)(wb + WB_FF2(l)), FFD, DIM, s2);
        cudaEventRecord(evW[4 * l + 3], s2);
    }
    convw_f16_s(w_logits, (__half*)(wb + WB_LOGITS), DIM, VOCAB, s2);
    cudaEventRecord(evW[16], s2);

    // main chain
    embed_kernel<<<SEQ * DIM / 256, 256>>>(tokens, emb, x);

    for (int l = 0; l < DEPTH; l++) {
        rmsnorm_split_f16_kernel<<<SEQ, 256>>>(x, gamma_attn + l * DIM, (__half*)ab);
        cudaStreamWaitEvent(0, evW[4 * l + 0], 0);
        BG_QKV<<<dim3(SEQ / 128, 3 * DIM / 128), 256, GEMM_SMEM>>>(
            ab, wb + WB_QKV(l), nullptr, qkv, nullptr, 3 * DIM, DIM / 64);
        qsplit_kernel<<<dim3(32, HEADS), 256>>>(qkv, qs);
        kvsplit_kernel<<<dim3(32, HEADS), 256>>>(qkv, ks, vs);
        flash_kernel<<<dim3(SEQ / 64, HEADS), 128, FL_SMEM>>>(qs, ks, vs, (__half*)ab);
        cudaStreamWaitEvent(0, evW[4 * l + 1], 0);
        BG_OUT<<<dim3(SEQ / 128, DIM / 128), 256, GEMM_SMEM>>>(
            ab, wb + WB_OUT(l), nullptr, x, nullptr, DIM, DIM / 64);
        // --- feedforward block ---
        rmsnorm_split_f16_kernel<<<SEQ, 256>>>(x, gamma_ff + l * DIM, (__half*)ab);
        cudaStreamWaitEvent(0, evW[4 * l + 2], 0);
        BG_FF1<<<dim3(SEQ / 128, FFD / 128), 256, GEMM_SMEM>>>(
            ab, wb + WB_FF1(l), b_ff1 + (size_t)l * FFD, nullptr, ab2, FFD, DIM / 64);
        cudaStreamWaitEvent(0, evW[4 * l + 3], 0);
        BG_FF2<<<dim3(SEQ / 128, DIM / 128), 256, GEMM_SMEM>>>(
            ab2, wb + WB_FF2(l), b_ff2 + (size_t)l * DIM, x, nullptr, DIM, FFD / 64);
    }

    // final norm + fp16 1-term logits GEMM
    rmsnorm_f16_kernel<<<SEQ, 256>>>(x, gamma_final, (__half*)ab);
    cudaStreamWaitEvent(0, evW[16], 0);
    BG_LOGIT<<<dim3(SEQ / 128, VOCAB / 128), 256, GEMM_SMEM>>>(
        ab, wb + WB_LOGITS, nullptr, out, nullptr, VOCAB, DIM / 64);
}

// round 15
// speedup vs baseline: 1.0989x; 1.0630x over previous
#include <cuda_runtime.h>
#include <cuda_bf16.h>
#include <cuda_fp16.h>
#include <math.h>
#include <float.h>
#include <stdint.h>

// ---------------- problem constants ----------------
#define SEQ   2048
#define DIM   1024
#define DEPTH 4
#define HEADS 16
#define DH    64
#define FFD   4096
#define VOCAB 32000

// ---------------- scratch (static device globals) ----------------
__device__ float g_x   [SEQ * DIM];
__device__ float g_qkv [SEQ * 3 * DIM];
__device__ __nv_bfloat16 g_ab [SEQ * 3 * DIM];
__device__ __nv_bfloat16 g_ab2[SEQ * 3 * FFD];
__device__ __nv_bfloat16 g_wb [133431296ull];
__device__ __align__(16) __nv_bfloat16 g_qs[6291456ull];  // Q tiles [h][ib][64][192] bf16 3-term
__device__ __align__(16) __nv_bfloat16 g_ks[6291456ull];  // K tiles [h][jb][192][64] bf16 3-term
__device__ __align__(16) __half        g_vs[2097152ull];  // V tiles [h][jb][64][64]  fp16 hi

// weight offsets in g_wb (2-byte elements) — all fp16 hi-only
#define WB_QKV(l)  ((size_t)(l) * 6291456ull)
#define WB_OUT(l)  (25165824ull + (size_t)(l) * 2097152ull)
#define WB_FF1(l)  (33554432ull + (size_t)(l) * 8388608ull)
#define WB_FF2(l)  (67108864ull + (size_t)(l) * 8388608ull)
#define WB_LOGITS  100663296ull

// ---------------- helpers ----------------
__device__ __forceinline__ uint32_t smem_u32(const void* p) {
    return (uint32_t)__cvta_generic_to_shared(p);
}
__device__ __forceinline__ void cp16(uint32_t s, const void* g) {
    asm volatile("cp.async.cg.shared.global [%0], [%1], 16;" :: "r"(s), "l"(g));
}
__device__ __forceinline__ uint32_t pack_bf16(float a, float b) {
    __nv_bfloat162 t = __floats2bfloat162_rn(a, b);
    return *(uint32_t*)&t;
}
__device__ __forceinline__ uint32_t pack_f16(float a, float b) {
    __half2 t = __floats2half2_rn(a, b);
    return *(uint32_t*)&t;
}

// ---------------- weight conv fp16 (hi only) ----------------
__global__ void __launch_bounds__(256) convw_f16_kernel(const float4* __restrict__ w,
                                                        __half* __restrict__ o,
                                                        long long KN4) {
    long long idx = (long long)blockIdx.x * 256 + threadIdx.x;
    if (idx >= KN4) return;
    float4 v = w[idx];
    union { __half u[4]; uint2 p; } h4;
    h4.u[0] = __float2half_rn(v.x); h4.u[1] = __float2half_rn(v.y);
    h4.u[2] = __float2half_rn(v.z); h4.u[3] = __float2half_rn(v.w);
    *(uint2*)(o + 4 * idx) = h4.p;
}

// ---------------- embed ----------------
__global__ void __launch_bounds__(256) embed_kernel(const int* __restrict__ tokens,
                                                    const float* __restrict__ emb,
                                                    float* __restrict__ x) {
    int idx = blockIdx.x * 256 + threadIdx.x;
    int row = idx >> 10;
    int d   = idx & 1023;
    x[idx] = emb[(size_t)tokens[row] * DIM + d];
}

// ---------------- rmsnorm + split fp16 2-term: A' = [hi | lo] ----
__global__ void __launch_bounds__(256) rmsnorm_split_f16_kernel(const float* __restrict__ x,
                                                                const float* __restrict__ gamma,
                                                                __half* __restrict__ ab) {
    int row = blockIdx.x;
    const float* xr = x + (size_t)row * DIM;
    float ss = 0.f;
    for (int i = threadIdx.x; i < DIM; i += 256) { float v = xr[i]; ss += v * v; }
    __shared__ float red[256];
    red[threadIdx.x] = ss;
    __syncthreads();
    for (int s = 128; s > 0; s >>= 1) {
        if (threadIdx.x < s) red[threadIdx.x] += red[threadIdx.x + s];
        __syncthreads();
    }
    float scale = 32.0f / fmaxf(sqrtf(red[0]), 1e-12f);
    __half* ar = ab + (size_t)row * (2 * DIM);
    for (int i = threadIdx.x; i < DIM; i += 256) {
        float v = xr[i] * scale * gamma[i];
        __half hi = __float2half_rn(v);
        __half lo = __float2half_rn(v - __half2float(hi));
        ar[i] = hi;
        ar[DIM + i] = lo;
    }
}

// ---------------- rmsnorm fp16 1-term (logits A) ----------------
__global__ void __launch_bounds__(256) rmsnorm_f16_kernel(const float* __restrict__ x,
                                                          const float* __restrict__ gamma,
                                                          __half* __restrict__ ab) {
    int row = blockIdx.x;
    const float* xr = x + (size_t)row * DIM;
    float ss = 0.f;
    for (int i = threadIdx.x; i < DIM; i += 256) { float v = xr[i]; ss += v * v; }
    __shared__ float red[256];
    red[threadIdx.x] = ss;
    __syncthreads();
    for (int s = 128; s > 0; s >>= 1) {
        if (threadIdx.x < s) red[threadIdx.x] += red[threadIdx.x + s];
        __syncthreads();
    }
    float scale = 32.0f / fmaxf(sqrtf(red[0]), 1e-12f);
    __half* ar = ab + (size_t)row * DIM;
    for (int i = threadIdx.x; i < DIM; i += 256)
        ar[i] = __float2half_rn(xr[i] * scale * gamma[i]);
}

// ---------------- fused Q/K/V split (rotary fused, shared trig) ----------------
// Q -> [h][ib][64][192] bf16 3-term (scaled 1/8); K -> [h][jb][192][64] bf16 3-term
// (transposed); V -> [h][jb][64][64] fp16 hi only.
#define L2_10000 13.287712379549449f
__global__ void __launch_bounds__(256) qkvsplit_kernel(const float* __restrict__ qkv,
                                                       __nv_bfloat16* __restrict__ Qsp,
                                                       __nv_bfloat16* __restrict__ Ksp,
                                                       __half* __restrict__ Vsp) {
    __shared__ float kt_s[64][65];
    int blk = blockIdx.x, h = blockIdx.y;
    int tid = threadIdx.x;
    __nv_bfloat16* qt = Qsp + ((size_t)h * 32 + blk) * (64 * 192);
    __nv_bfloat16* kt = Ksp + ((size_t)h * 32 + blk) * (192 * 64);
    __half*        vt = Vsp + ((size_t)h * 32 + blk) * (64 * 64);
    #pragma unroll
    for (int l = 0; l < 16; l++) {
        int e = tid + l * 256;
        int i = e >> 6, d = e & 63;
        int pos = blk * 64 + i;
        const float* base = qkv + (size_t)pos * (3 * DIM);
        int j = d & 31;
        float inv = exp2f((float)j * (-L2_10000 / 32.0f));
        float fr = (float)pos * inv;
        float c, s;
        sincosf(fr, &s, &c);
        // Q (scaled)
        {
            const float* qrow = base + h * DH;
            float x = qrow[d], other = qrow[d ^ 32];
            float val = ((d < 32) ? (x * c - other * s) : (x * c + other * s)) * 0.125f;
            __nv_bfloat16 hi = __float2bfloat16_rn(val);
            __nv_bfloat16 lo = __float2bfloat16_rn(val - __bfloat162float(hi));
            qt[(size_t)i * 192 + d]       = hi;
            qt[(size_t)i * 192 + 64 + d]  = lo;
            qt[(size_t)i * 192 + 128 + d] = hi;
        }
        // K (into smem for transpose)
        {
            const float* krow = base + (HEADS + h) * DH;
            float x = krow[d], other = krow[d ^ 32];
            kt_s[d][i] = (d < 32) ? (x * c - other * s) : (x * c + other * s);
        }
        // V (fp16 hi only)
        vt[(size_t)i * 64 + d] = __float2half_rn(base[(2 * HEADS + h) * DH + d]);
    }
    __syncthreads();
    #pragma unroll
    for (int l = 0; l < 16; l++) {
        int e = tid + l * 256;
        int d = e >> 6, jj = e & 63;
        float val = kt_s[d][jj];
        __nv_bfloat16 hi = __float2bfloat16_rn(val);
        __nv_bfloat16 lo = __float2bfloat16_rn(val - __bfloat162float(hi));
        kt[(size_t)d * 64 + jj]         = hi;
        kt[(size_t)(64 + d) * 64 + jj]  = hi;
        kt[(size_t)(128 + d) * 64 + jj] = lo;
    }
}

// ---------------- mma primitives ----------------
#define LDSM4(R0,R1,R2,R3,addr) \
    asm volatile("ldmatrix.sync.aligned.m8n8.x4.shared.b16 {%0,%1,%2,%3},[%4];" \
        : "=r"(R0),"=r"(R1),"=r"(R2),"=r"(R3) : "r"(addr))
#define LDSM4T(R0,R1,R2,R3,addr) \
    asm volatile("ldmatrix.sync.aligned.m8n8.x4.trans.shared.b16 {%0,%1,%2,%3},[%4];" \
        : "=r"(R0),"=r"(R1),"=r"(R2),"=r"(R3) : "r"(addr))

template<bool F16>
__device__ __forceinline__ void mma_op(float* d, const uint32_t* a, uint32_t b0, uint32_t b1) {
    if (F16)
        asm volatile("mma.sync.aligned.m16n8k16.row.col.f32.f16.f16.f32 "
            "{%0,%1,%2,%3},{%4,%5,%6,%7},{%8,%9},{%0,%1,%2,%3};"
            : "+f"(d[0]),"+f"(d[1]),"+f"(d[2]),"+f"(d[3])
            : "r"(a[0]),"r"(a[1]),"r"(a[2]),"r"(a[3]),"r"(b0),"r"(b1));
    else
        asm volatile("mma.sync.aligned.m16n8k16.row.col.f32.bf16.bf16.f32 "
            "{%0,%1,%2,%3},{%4,%5,%6,%7},{%8,%9},{%0,%1,%2,%3};"
            : "+f"(d[0]),"+f"(d[1]),"+f"(d[2]),"+f"(d[3])
            : "r"(a[0]),"r"(a[1]),"r"(a[2]),"r"(a[3]),"r"(b0),"r"(b1));
}

// ---------------- tensor-core GEMM (K-chunk 64, 3 stages, frag dbuf) ----
// SPLITM: 0 = fp32 C (optional RES), 2 = fp16 2-term A'-format
#define A_STG_B 18432
#define B_STG_B 17408
#define SSTG_B  (A_STG_B + B_STG_B)
#define GEMM_SMEM (3 * SSTG_B)

template<int TERMS, bool F16, bool BIAS, bool RES, bool GELU, int SPLITM>
__global__ void __launch_bounds__(256, 2)
bgemm_kernel(const __nv_bfloat16* __restrict__ A,
             const __nv_bfloat16* __restrict__ B,
             const float* __restrict__ bias,
             float* __restrict__ C,
             __nv_bfloat16* __restrict__ Cs,
             int N, int Ku64)
{
    extern __shared__ __align__(16) __nv_bfloat16 sm[];
    uint32_t sbase = smem_u32(sm);

    int tid  = threadIdx.x;
    int lane = tid & 31;
    int warp = tid >> 5;
    int wm = warp >> 2;
    int wn = warp & 3;
    int bm = blockIdx.x * 128;
    int bn = blockIdx.y * 128;
    int Astride = TERMS * Ku64 * 64;

    const char* gAbase = (const char*)(A + (size_t)bm * Astride);
    const char* gBbase = (const char*)(B + bn);

    uint32_t aFrag = (uint32_t)(((wm * 64 + (lane & 15)) * 72 + (lane >> 4) * 8) * 2);
    uint32_t bFrag = (uint32_t)(A_STG_B + ((lane & 15) * 136 + wn * 32 + (lane >> 4) * 8) * 2);

    float acc[4][4][4];
    #pragma unroll
    for (int i = 0; i < 4; i++)
        #pragma unroll
        for (int j = 0; j < 4; j++)
            #pragma unroll
            for (int k = 0; k < 4; k++) acc[i][j][k] = 0.f;

    int steps = TERMS * Ku64;

    auto load_stage = [&](int t) {
        uint32_t so = sbase + (uint32_t)(t % 3) * SSTG_B;
        int bs = (t < Ku64) ? t : t - Ku64;
        const char* aP = gAbase + (size_t)t * 128;
        const char* bP = gBbase + (size_t)bs * ((size_t)N * 128);
        #pragma unroll
        for (int j = 0; j < 4; j++) {
            int i = tid + j * 256;
            cp16(so + (uint32_t)(((i >> 3) * 72 + (i & 7) * 8) * 2),
                 aP + (size_t)(i >> 3) * Astride * 2 + (i & 7) * 16);
            cp16(so + (uint32_t)(A_STG_B + ((i >> 4) * 136 + (i & 15) * 8) * 2),
                 bP + (size_t)(i >> 4) * N * 2 + (i & 15) * 16);
        }
        asm volatile("cp.async.commit_group;" ::: "memory");
    };

    load_stage(0);
    load_stage(1);

    uint32_t af[2][16], bf[2][8];

    auto ldsA = [&](uint32_t* f, uint32_t stg, int kk) {
        #pragma unroll
        for (int mt = 0; mt < 4; mt++) {
            uint32_t addr = stg + aFrag + mt * (16 * 72 * 2) + kk * 32;
            LDSM4(f[mt * 4 + 0], f[mt * 4 + 1], f[mt * 4 + 2], f[mt * 4 + 3], addr);
        }
    };
    auto ldsB = [&](uint32_t* f, uint32_t stg, int kk) {
        #pragma unroll
        for (int p = 0; p < 2; p++) {
            uint32_t addr = stg + bFrag + p * 32 + kk * (16 * 136 * 2);
            LDSM4T(f[p * 4 + 0], f[p * 4 + 1], f[p * 4 + 2], f[p * 4 + 3], addr);
        }
    };

    for (int t = 0; t < steps; t++) {
        if (t + 1 < steps) asm volatile("cp.async.wait_group 1;" ::: "memory");
        else               asm volatile("cp.async.wait_group 0;" ::: "memory");
        __syncthreads();
        if (t + 2 < steps) load_stage(t + 2);

        uint32_t stg = sbase + (uint32_t)(t % 3) * SSTG_B;
        ldsA(af[0], stg, 0);
        ldsB(bf[0], stg, 0);
        #pragma unroll
        for (int kk = 0; kk < 4; kk++) {
            int cur = kk & 1, nxt = cur ^ 1;
            if (kk < 3) { ldsA(af[nxt], stg, kk + 1); ldsB(bf[nxt], stg, kk + 1); }
            #pragma unroll
            for (int mt = 0; mt < 4; mt++) {
                #pragma unroll
                for (int nt = 0; nt < 4; nt++) {
                    uint32_t b0 = bf[cur][(nt >> 1) * 4 + (nt & 1) * 2];
                    uint32_t b1 = bf[cur][(nt >> 1) * 4 + (nt & 1) * 2 + 1];
                    mma_op<F16>(acc[mt][nt], &af[cur][mt * 4], b0, b1);
                }
            }
        }
    }

    int row0 = bm + wm * 64;
    int col0 = bn + wn * 32;
    #pragma unroll
    for (int mt = 0; mt < 4; mt++) {
        #pragma unroll
        for (int nt = 0; nt < 4; nt++) {
            int r = row0 + mt * 16 + (lane >> 2);
            int c = col0 + nt * 8 + (lane & 3) * 2;
            #pragma unroll
            for (int half = 0; half < 2; half++) {
                int rr = r + half * 8;
                #pragma unroll
                for (int e = 0; e < 2; e++) {
                    float val = acc[mt][nt][half * 2 + e];
                    int cc = c + e;
                    if (BIAS) val += bias[cc];
                    if (GELU) val = 0.5f * val * (1.0f + erff(val * 0.70710678118654752f));
                    if (SPLITM == 2) {
                        __half* Ch = (__half*)Cs;
                        __half hi = __float2half_rn(val);
                        __half lo = __float2half_rn(val - __half2float(hi));
                        size_t base = (size_t)rr * (2 * (size_t)N);
                        Ch[base + cc] = hi;
                        Ch[base + N + cc] = lo;
                    } else {
                        size_t off = (size_t)rr * N + cc;
                        if (RES) val += C[off];
                        C[off] = val;
                    }
                }
            }
        }
    }
}

// ---------------- tensor-core flash attention: QK 3-term bf16, PV 2-term fp16 --------
// grid (SEQ/64, HEADS), 128 threads (4 warps x 16 Q-rows), 2 CTA/SM.
// smem: Qs [64][200] bf16, Ks [192][72] bf16, Vs [64][72] fp16
#define FLQ_E (64 * 200)
#define FLK_E (192 * 72)
#define FLV_E (64 * 72)
#define FL_SMEM ((FLQ_E + FLK_E + FLV_E) * 2)

__global__ void __launch_bounds__(128) flash_kernel(const __nv_bfloat16* __restrict__ Qsp,
                                                    const __nv_bfloat16* __restrict__ Ksp,
                                                    const __half* __restrict__ Vsp,
                                                    __half* __restrict__ ab) {
    extern __shared__ __align__(16) __nv_bfloat16 fsm[];
    uint32_t qsmem = smem_u32(fsm);
    uint32_t ksmem = qsmem + FLQ_E * 2;
    uint32_t vsmem = ksmem + FLK_E * 2;

    int br = gridDim.x - 1 - blockIdx.x;     // heavy blocks first
    int h  = blockIdx.y;
    int tid = threadIdx.x, lane = tid & 31, warp = tid >> 5;

    const char* qg = (const char*)(Qsp + ((size_t)h * 32 + br) * (64 * 192));
    #pragma unroll
    for (int l = 0; l < 12; l++) {
        int c = tid + l * 128;
        int row = c / 24, col = c - row * 24;
        cp16(qsmem + (uint32_t)(row * 400 + col * 16), qg + (size_t)row * 384 + col * 16);
    }
    asm volatile("cp.async.commit_group;" ::: "memory");
    asm volatile("cp.async.wait_group 0;" ::: "memory");
    __syncthreads();

    uint32_t qf[12][4];
    uint32_t qbase = qsmem + (uint32_t)(((warp * 16 + (lane & 15)) * 200 + (lane >> 4) * 8) * 2);
    #pragma unroll
    for (int s = 0; s < 12; s++)
        LDSM4(qf[s][0], qf[s][1], qf[s][2], qf[s][3], qbase + s * 32);

    uint32_t ksb = ksmem + (uint32_t)(((lane & 15) * 72 + (lane >> 4) * 8) * 2);
    uint32_t vsb = vsmem + (uint32_t)(((lane & 15) * 72 + (lane >> 4) * 8) * 2);

    float O[8][4];
    float run_max[2] = {-1e30f, -1e30f};
    float run_sum[2] = {0.f, 0.f};
    #pragma unroll
    for (int nt = 0; nt < 8; nt++)
        #pragma unroll
        for (int e = 0; e < 4; e++) O[nt][e] = 0.f;

    for (int kb = 0; kb <= br; kb++) {
        __syncthreads();
        const char* kg = (const char*)(Ksp + ((size_t)h * 32 + kb) * (192 * 64));
        const char* vg = (const char*)(Vsp + ((size_t)h * 32 + kb) * (64 * 64));
        #pragma unroll
        for (int l = 0; l < 12; l++) {
            int c = tid + l * 128;
            int row = c >> 3, col = c & 7;
            cp16(ksmem + (uint32_t)(row * 144 + col * 16), kg + (size_t)row * 128 + col * 16);
        }
        #pragma unroll
        for (int l = 0; l < 4; l++) {
            int c = tid + l * 128;
            int row = c >> 3, col = c & 7;
            cp16(vsmem + (uint32_t)(row * 144 + col * 16), vg + (size_t)row * 128 + col * 16);
        }
        asm volatile("cp.async.commit_group;" ::: "memory");
        asm volatile("cp.async.wait_group 0;" ::: "memory");
        __syncthreads();

        // ---- S = Q K^T (bf16 3-term, 12 steps) ----
        float S[8][4];
        #pragma unroll
        for (int nt = 0; nt < 8; nt++)
            #pragma unroll
            for (int e = 0; e < 4; e++) S[nt][e] = 0.f;
        #pragma unroll
        for (int s = 0; s < 12; s++) {
            uint32_t bfr[4][4];
            #pragma unroll
            for (int p = 0; p < 4; p++)
                LDSM4T(bfr[p][0], bfr[p][1], bfr[p][2], bfr[p][3],
                       ksb + p * 32 + s * (16 * 72 * 2));
            #pragma unroll
            for (int nt = 0; nt < 8; nt++) {
                uint32_t b0 = bfr[nt >> 1][(nt & 1) * 2];
                uint32_t b1 = bfr[nt >> 1][(nt & 1) * 2 + 1];
                mma_op<false>(S[nt], qf[s], b0, b1);
            }
        }

        if (kb == br) {
            #pragma unroll
            for (int nt = 0; nt < 8; nt++)
                #pragma unroll
                for (int e = 0; e < 4; e++) {
                    int rowl = warp * 16 + (lane >> 2) + (e >> 1) * 8;
                    int coll = nt * 8 + (lane & 3) * 2 + (e & 1);
                    if (coll > rowl) S[nt][e] = -1e30f;
                }
        }

        float alpha[2];
        #pragma unroll
        for (int half = 0; half < 2; half++) {
            float m = -1e30f;
            #pragma unroll
            for (int nt = 0; nt < 8; nt++)
                m = fmaxf(m, fmaxf(S[nt][half * 2], S[nt][half * 2 + 1]));
            m = fmaxf(m, __shfl_xor_sync(0xffffffffu, m, 1));
            m = fmaxf(m, __shfl_xor_sync(0xffffffffu, m, 2));
            float nm = fmaxf(run_max[half], m);
            alpha[half] = __expf(run_max[half] - nm);
            run_max[half] = nm;
            float ps = 0.f;
            #pragma unroll
            for (int nt = 0; nt < 8; nt++) {
                float p0 = __expf(S[nt][half * 2]     - nm);
                float p1 = __expf(S[nt][half * 2 + 1] - nm);
                S[nt][half * 2]     = p0;
                S[nt][half * 2 + 1] = p1;
                ps += p0 + p1;
            }
            ps += __shfl_xor_sync(0xffffffffu, ps, 1);
            ps += __shfl_xor_sync(0xffffffffu, ps, 2);
            run_sum[half] = run_sum[half] * alpha[half] + ps;
        }
        #pragma unroll
        for (int nt = 0; nt < 8; nt++) {
            O[nt][0] *= alpha[0]; O[nt][1] *= alpha[0];
            O[nt][2] *= alpha[1]; O[nt][3] *= alpha[1];
        }

        // ---- P fragments fp16 hi/lo (exact split; P in [0,1]) ----
        uint32_t phi[4][4], plo[4][4];
        #pragma unroll
        for (int t = 0; t < 4; t++) {
            #pragma unroll
            for (int g = 0; g < 2; g++) {
                float c0 = S[2 * t + g][0], c1 = S[2 * t + g][1];
                float c2 = S[2 * t + g][2], c3 = S[2 * t + g][3];
                __half h0 = __float2half_rn(c0);
                __half h1 = __float2half_rn(c1);
                __half h2 = __float2half_rn(c2);
                __half h3 = __float2half_rn(c3);
                __half2 p01 = __halves2half2(h0, h1);
                __half2 p23 = __halves2half2(h2, h3);
                phi[t][g * 2 + 0] = *(uint32_t*)&p01;
                phi[t][g * 2 + 1] = *(uint32_t*)&p23;
                plo[t][g * 2 + 0] = pack_f16(c0 - __half2float(h0), c1 - __half2float(h1));
                plo[t][g * 2 + 1] = pack_f16(c2 - __half2float(h2), c3 - __half2float(h3));
            }
        }

        // ---- O += P V (fp16 2-term: 8 steps, V block reused) ----
        #pragma unroll
        for (int s = 0; s < 8; s++) {
            uint32_t bfr[4][4];
            #pragma unroll
            for (int p = 0; p < 4; p++)
                LDSM4T(bfr[p][0], bfr[p][1], bfr[p][2], bfr[p][3],
                       vsb + p * 32 + (s & 3) * (16 * 72 * 2));
            const uint32_t* a = (s < 4) ? phi[s] : plo[s - 4];
            #pragma unroll
            for (int nt = 0; nt < 8; nt++) {
                uint32_t b0 = bfr[nt >> 1][(nt & 1) * 2];
                uint32_t b1 = bfr[nt >> 1][(nt & 1) * 2 + 1];
                mma_op<true>(O[nt], a, b0, b1);
            }
        }
    }

    // ---- normalize + write fp16 2-term rows (stride 2*DIM) ----
    float inv0 = 1.0f / run_sum[0];
    float inv1 = 1.0f / run_sum[1];
    #pragma unroll
    for (int half = 0; half < 2; half++) {
        int row = br * 64 + warp * 16 + (lane >> 2) + half * 8;
        size_t base = (size_t)row * (2 * DIM);
        float inv = half ? inv1 : inv0;
        #pragma unroll
        for (int nt = 0; nt < 8; nt++) {
            int col = h * DH + nt * 8 + (lane & 3) * 2;
            float v0 = O[nt][half * 2]     * inv;
            float v1 = O[nt][half * 2 + 1] * inv;
            __half h0 = __float2half_rn(v0);
            __half h1 = __float2half_rn(v1);
            __half l0 = __float2half_rn(v0 - __half2float(h0));
            __half l1 = __float2half_rn(v1 - __half2float(h1));
            *(__half2*)(ab + base + col)       = __halves2half2(h0, h1);
            *(__half2*)(ab + base + DIM + col) = __halves2half2(l0, l1);
        }
    }
}

// ---------------- launch ----------------
static inline void convw_f16_s(const float* src, __half* dst, long long K, long long N,
                               cudaStream_t st) {
    long long KN4 = K * N / 4;
    convw_f16_kernel<<<(unsigned)((KN4 + 255) / 256), 256, 0, st>>>((const float4*)src, dst, KN4);
}

#define BG_QKV   bgemm_kernel<2, true, false, false, false, 0>
#define BG_OUT   bgemm_kernel<2, true, false, true,  false, 0>
#define BG_FF1   bgemm_kernel<2, true, true,  false, true,  2>
#define BG_FF2   bgemm_kernel<2, true, true,  true,  false, 0>
#define BG_LOGIT bgemm_kernel<1, true, false, false, false, 0>

extern "C" void kernel_launch(void* const* d_in, const int* in_sizes, int n_in,
                              void* d_out, int out_size) {
    const int*   tokens      = (const int*)  d_in[0];
    const float* emb         = (const float*)d_in[1];
    const float* gamma_attn  = (const float*)d_in[2];
    const float* w_qkv       = (const float*)d_in[3];
    const float* w_out       = (const float*)d_in[4];
    const float* gamma_ff    = (const float*)d_in[5];
    const float* w_ff1       = (const float*)d_in[6];
    const float* b_ff1       = (const float*)d_in[7];
    const float* w_ff2       = (const float*)d_in[8];
    const float* b_ff2       = (const float*)d_in[9];
    const float* gamma_final = (const float*)d_in[10];
    const float* w_logits    = (const float*)d_in[11];
    float* out = (float*)d_out;

    float *x, *qkv;
    __nv_bfloat16 *ab, *ab2, *wb, *qs, *ks;
    __half *vs;
    cudaGetSymbolAddress((void**)&x,   g_x);
    cudaGetSymbolAddress((void**)&qkv, g_qkv);
    cudaGetSymbolAddress((void**)&ab,  g_ab);
    cudaGetSymbolAddress((void**)&ab2, g_ab2);
    cudaGetSymbolAddress((void**)&wb,  g_wb);
    cudaGetSymbolAddress((void**)&qs,  g_qs);
    cudaGetSymbolAddress((void**)&ks,  g_ks);
    cudaGetSymbolAddress((void**)&vs,  g_vs);

    cudaFuncSetAttribute(flash_kernel, cudaFuncAttributeMaxDynamicSharedMemorySize, FL_SMEM);
    cudaFuncSetAttribute(BG_QKV,   cudaFuncAttributeMaxDynamicSharedMemorySize, GEMM_SMEM);
    cudaFuncSetAttribute(BG_OUT,   cudaFuncAttributeMaxDynamicSharedMemorySize, GEMM_SMEM);
    cudaFuncSetAttribute(BG_FF1,   cudaFuncAttributeMaxDynamicSharedMemorySize, GEMM_SMEM);
    cudaFuncSetAttribute(BG_FF2,   cudaFuncAttributeMaxDynamicSharedMemorySize, GEMM_SMEM);
    cudaFuncSetAttribute(BG_LOGIT, cudaFuncAttributeMaxDynamicSharedMemorySize, GEMM_SMEM);

    // lazily-created side stream + events
    static cudaStream_t s2 = nullptr;
    static cudaEvent_t evFork;
    static cudaEvent_t evW[17];
    if (!s2) {
        cudaStreamCreateWithFlags(&s2, cudaStreamNonBlocking);
        cudaEventCreateWithFlags(&evFork, cudaEventDisableTiming);
        for (int i = 0; i < 17; i++)
            cudaEventCreateWithFlags(&evW[i], cudaEventDisableTiming);
    }

    // fork: weight conversions on s2
    cudaEventRecord(evFork, 0);
    cudaStreamWaitEvent(s2, evFork, 0);
    for (int l = 0; l < DEPTH; l++) {
        convw_f16_s(w_qkv + (size_t)l * DIM * 3 * DIM, (__half*)(wb + WB_QKV(l)), DIM, 3 * DIM, s2);
        cudaEventRecord(evW[4 * l + 0], s2);
        convw_f16_s(w_out + (size_t)l * DIM * DIM, (__half*)(wb + WB_OUT(l)), DIM, DIM, s2);
        cudaEventRecord(evW[4 * l + 1], s2);
        convw_f16_s(w_ff1 + (size_t)l * DIM * FFD, (__half*)(wb + WB_FF1(l)), DIM, FFD, s2);
        cudaEventRecord(evW[4 * l + 2], s2);
        convw_f16_s(w_ff2 + (size_t)l * FFD * DIM, (__half*)(wb + WB_FF2(l)), FFD, DIM, s2);
        cudaEventRecord(evW[4 * l + 3], s2);
    }
    convw_f16_s(w_logits, (__half*)(wb + WB_LOGITS), DIM, VOCAB, s2);
    cudaEventRecord(evW[16], s2);

    // main chain
    embed_kernel<<<SEQ * DIM / 256, 256>>>(tokens, emb, x);

    for (int l = 0; l < DEPTH; l++) {
        rmsnorm_split_f16_kernel<<<SEQ, 256>>>(x, gamma_attn + l * DIM, (__half*)ab);
        cudaStreamWaitEvent(0, evW[4 * l + 0], 0);
        BG_QKV<<<dim3(SEQ / 128, 3 * DIM / 128), 256, GEMM_SMEM>>>(
            ab, wb + WB_QKV(l), nullptr, qkv, nullptr, 3 * DIM, DIM / 64);
        qkvsplit_kernel<<<dim3(32, HEADS), 256>>>(qkv, qs, ks, vs);
        flash_kernel<<<dim3(SEQ / 64, HEADS), 128, FL_SMEM>>>(qs, ks, vs, (__half*)ab);
        cudaStreamWaitEvent(0, evW[4 * l + 1], 0);
        BG_OUT<<<dim3(SEQ / 128, DIM / 128), 256, GEMM_SMEM>>>(
            ab, wb + WB_OUT(l), nullptr, x, nullptr, DIM, DIM / 64);
        // --- feedforward block ---
        rmsnorm_split_f16_kernel<<<SEQ, 256>>>(x, gamma_ff + l * DIM, (__half*)ab);
        cudaStreamWaitEvent(0, evW[4 * l + 2], 0);
        BG_FF1<<<dim3(SEQ / 128, FFD / 128), 256, GEMM_SMEM>>>(
            ab, wb + WB_FF1(l), b_ff1 + (size_t)l * FFD, nullptr, ab2, FFD, DIM / 64);
        cudaStreamWaitEvent(0, evW[4 * l + 3], 0);
        BG_FF2<<<dim3(SEQ / 128, DIM / 128), 256, GEMM_SMEM>>>(
            ab2, wb + WB_FF2(l), b_ff2 + (size_t)l * DIM, x, nullptr, DIM, FFD / 64);
    }

    // final norm + fp16 1-term logits GEMM
    rmsnorm_f16_kernel<<<SEQ, 256>>>(x, gamma_final, (__half*)ab);
    cudaStreamWaitEvent(0, evW[16], 0);
    BG_LOGIT<<<dim3(SEQ / 128, VOCAB / 128), 256, GEMM_SMEM>>>(
        ab, wb + WB_LOGITS, nullptr, out, nullptr, VOCAB, DIM / 64);
}

// round 16
// speedup vs baseline: 1.3772x; 1.2533x over previous
#include <cuda_runtime.h>
#include <cuda_bf16.h>
#include <cuda_fp16.h>
#include <math.h>
#include <float.h>
#include <stdint.h>

// ---------------- problem constants ----------------
#define SEQ   2048
#define DIM   1024
#define DEPTH 4
#define HEADS 16
#define DH    64
#define FFD   4096
#define VOCAB 32000

// ---------------- scratch (static device globals) ----------------
__device__ float g_x   [SEQ * DIM];
__device__ float g_qkv [SEQ * 3 * DIM];
__device__ __nv_bfloat16 g_ab [SEQ * 3 * DIM];
__device__ __nv_bfloat16 g_ab2[SEQ * 3 * FFD];
__device__ __nv_bfloat16 g_wb [133431296ull];
__device__ __align__(16) __nv_bfloat16 g_qs[6291456ull];  // Q tiles [h][ib][64][192] bf16 3-term
__device__ __align__(16) __nv_bfloat16 g_ks[6291456ull];  // K tiles [h][jb][192][64] bf16 3-term
__device__ __align__(16) __half        g_vs[2097152ull];  // V tiles [h][jb][64][64]  fp16 hi

// weight offsets in g_wb (2-byte elements) — all fp16 hi-only
#define WB_QKV(l)  ((size_t)(l) * 6291456ull)
#define WB_OUT(l)  (25165824ull + (size_t)(l) * 2097152ull)
#define WB_FF1(l)  (33554432ull + (size_t)(l) * 8388608ull)
#define WB_FF2(l)  (67108864ull + (size_t)(l) * 8388608ull)
#define WB_LOGITS  100663296ull

// ---------------- helpers ----------------
__device__ __forceinline__ uint32_t smem_u32(const void* p) {
    return (uint32_t)__cvta_generic_to_shared(p);
}
__device__ __forceinline__ void cp16(uint32_t s, const void* g) {
    asm volatile("cp.async.cg.shared.global [%0], [%1], 16;" :: "r"(s), "l"(g));
}
__device__ __forceinline__ uint32_t pack_bf16(float a, float b) {
    __nv_bfloat162 t = __floats2bfloat162_rn(a, b);
    return *(uint32_t*)&t;
}
__device__ __forceinline__ uint32_t pack_f16(float a, float b) {
    __half2 t = __floats2half2_rn(a, b);
    return *(uint32_t*)&t;
}

// ---------------- weight conv fp16 (hi only) ----------------
__global__ void __launch_bounds__(256) convw_f16_kernel(const float4* __restrict__ w,
                                                        __half* __restrict__ o,
                                                        long long KN4) {
    long long idx = (long long)blockIdx.x * 256 + threadIdx.x;
    if (idx >= KN4) return;
    float4 v = w[idx];
    union { __half u[4]; uint2 p; } h4;
    h4.u[0] = __float2half_rn(v.x); h4.u[1] = __float2half_rn(v.y);
    h4.u[2] = __float2half_rn(v.z); h4.u[3] = __float2half_rn(v.w);
    *(uint2*)(o + 4 * idx) = h4.p;
}

// ---------------- embed ----------------
__global__ void __launch_bounds__(256) embed_kernel(const int* __restrict__ tokens,
                                                    const float* __restrict__ emb,
                                                    float* __restrict__ x) {
    int idx = blockIdx.x * 256 + threadIdx.x;
    int row = idx >> 10;
    int d   = idx & 1023;
    x[idx] = emb[(size_t)tokens[row] * DIM + d];
}

// ---------------- rmsnorm + split fp16 2-term: A' = [hi | lo] ----
__global__ void __launch_bounds__(256) rmsnorm_split_f16_kernel(const float* __restrict__ x,
                                                                const float* __restrict__ gamma,
                                                                __half* __restrict__ ab) {
    int row = blockIdx.x;
    const float* xr = x + (size_t)row * DIM;
    float ss = 0.f;
    for (int i = threadIdx.x; i < DIM; i += 256) { float v = xr[i]; ss += v * v; }
    __shared__ float red[256];
    red[threadIdx.x] = ss;
    __syncthreads();
    for (int s = 128; s > 0; s >>= 1) {
        if (threadIdx.x < s) red[threadIdx.x] += red[threadIdx.x + s];
        __syncthreads();
    }
    float scale = 32.0f / fmaxf(sqrtf(red[0]), 1e-12f);
    __half* ar = ab + (size_t)row * (2 * DIM);
    for (int i = threadIdx.x; i < DIM; i += 256) {
        float v = xr[i] * scale * gamma[i];
        __half hi = __float2half_rn(v);
        __half lo = __float2half_rn(v - __half2float(hi));
        ar[i] = hi;
        ar[DIM + i] = lo;
    }
}

// ---------------- rmsnorm fp16 1-term ----------------
__global__ void __launch_bounds__(256) rmsnorm_f16_kernel(const float* __restrict__ x,
                                                          const float* __restrict__ gamma,
                                                          __half* __restrict__ ab) {
    int row = blockIdx.x;
    const float* xr = x + (size_t)row * DIM;
    float ss = 0.f;
    for (int i = threadIdx.x; i < DIM; i += 256) { float v = xr[i]; ss += v * v; }
    __shared__ float red[256];
    red[threadIdx.x] = ss;
    __syncthreads();
    for (int s = 128; s > 0; s >>= 1) {
        if (threadIdx.x < s) red[threadIdx.x] += red[threadIdx.x + s];
        __syncthreads();
    }
    float scale = 32.0f / fmaxf(sqrtf(red[0]), 1e-12f);
    __half* ar = ab + (size_t)row * DIM;
    for (int i = threadIdx.x; i < DIM; i += 256)
        ar[i] = __float2half_rn(xr[i] * scale * gamma[i]);
}

// ---------------- fused Q/K/V split (rotary fused, shared trig) ----------------
#define L2_10000 13.287712379549449f
__global__ void __launch_bounds__(256) qkvsplit_kernel(const float* __restrict__ qkv,
                                                       __nv_bfloat16* __restrict__ Qsp,
                                                       __nv_bfloat16* __restrict__ Ksp,
                                                       __half* __restrict__ Vsp) {
    __shared__ float kt_s[64][65];
    int blk = blockIdx.x, h = blockIdx.y;
    int tid = threadIdx.x;
    __nv_bfloat16* qt = Qsp + ((size_t)h * 32 + blk) * (64 * 192);
    __nv_bfloat16* kt = Ksp + ((size_t)h * 32 + blk) * (192 * 64);
    __half*        vt = Vsp + ((size_t)h * 32 + blk) * (64 * 64);
    #pragma unroll
    for (int l = 0; l < 16; l++) {
        int e = tid + l * 256;
        int i = e >> 6, d = e & 63;
        int pos = blk * 64 + i;
        const float* base = qkv + (size_t)pos * (3 * DIM);
        int j = d & 31;
        float inv = exp2f((float)j * (-L2_10000 / 32.0f));
        float fr = (float)pos * inv;
        float c, s;
        sincosf(fr, &s, &c);
        {
            const float* qrow = base + h * DH;
            float x = qrow[d], other = qrow[d ^ 32];
            float val = ((d < 32) ? (x * c - other * s) : (x * c + other * s)) * 0.125f;
            __nv_bfloat16 hi = __float2bfloat16_rn(val);
            __nv_bfloat16 lo = __float2bfloat16_rn(val - __bfloat162float(hi));
            qt[(size_t)i * 192 + d]       = hi;
            qt[(size_t)i * 192 + 64 + d]  = lo;
            qt[(size_t)i * 192 + 128 + d] = hi;
        }
        {
            const float* krow = base + (HEADS + h) * DH;
            float x = krow[d], other = krow[d ^ 32];
            kt_s[d][i] = (d < 32) ? (x * c - other * s) : (x * c + other * s);
        }
        vt[(size_t)i * 64 + d] = __float2half_rn(base[(2 * HEADS + h) * DH + d]);
    }
    __syncthreads();
    #pragma unroll
    for (int l = 0; l < 16; l++) {
        int e = tid + l * 256;
        int d = e >> 6, jj = e & 63;
        float val = kt_s[d][jj];
        __nv_bfloat16 hi = __float2bfloat16_rn(val);
        __nv_bfloat16 lo = __float2bfloat16_rn(val - __bfloat162float(hi));
        kt[(size_t)d * 64 + jj]         = hi;
        kt[(size_t)(64 + d) * 64 + jj]  = hi;
        kt[(size_t)(128 + d) * 64 + jj] = lo;
    }
}

// ---------------- mma primitives ----------------
#define LDSM4(R0,R1,R2,R3,addr) \
    asm volatile("ldmatrix.sync.aligned.m8n8.x4.shared.b16 {%0,%1,%2,%3},[%4];" \
        : "=r"(R0),"=r"(R1),"=r"(R2),"=r"(R3) : "r"(addr))
#define LDSM4T(R0,R1,R2,R3,addr) \
    asm volatile("ldmatrix.sync.aligned.m8n8.x4.trans.shared.b16 {%0,%1,%2,%3},[%4];" \
        : "=r"(R0),"=r"(R1),"=r"(R2),"=r"(R3) : "r"(addr))

template<bool F16>
__device__ __forceinline__ void mma_op(float* d, const uint32_t* a, uint32_t b0, uint32_t b1) {
    if (F16)
        asm volatile("mma.sync.aligned.m16n8k16.row.col.f32.f16.f16.f32 "
            "{%0,%1,%2,%3},{%4,%5,%6,%7},{%8,%9},{%0,%1,%2,%3};"
            : "+f"(d[0]),"+f"(d[1]),"+f"(d[2]),"+f"(d[3])
            : "r"(a[0]),"r"(a[1]),"r"(a[2]),"r"(a[3]),"r"(b0),"r"(b1));
    else
        asm volatile("mma.sync.aligned.m16n8k16.row.col.f32.bf16.bf16.f32 "
            "{%0,%1,%2,%3},{%4,%5,%6,%7},{%8,%9},{%0,%1,%2,%3};"
            : "+f"(d[0]),"+f"(d[1]),"+f"(d[2]),"+f"(d[3])
            : "r"(a[0]),"r"(a[1]),"r"(a[2]),"r"(a[3]),"r"(b0),"r"(b1));
}

// ---------------- tensor-core GEMM (K-chunk 64, 3 stages, frag dbuf) ----
// SPLITM: 0 = fp32 C (optional RES), 2 = fp16 2-term A'-format, 3 = fp16 1-term
#define A_STG_B 18432
#define B_STG_B 17408
#define SSTG_B  (A_STG_B + B_STG_B)
#define GEMM_SMEM (3 * SSTG_B)

template<int TERMS, bool F16, bool BIAS, bool RES, bool GELU, int SPLITM>
__global__ void __launch_bounds__(256, 2)
bgemm_kernel(const __nv_bfloat16* __restrict__ A,
             const __nv_bfloat16* __restrict__ B,
             const float* __restrict__ bias,
             float* __restrict__ C,
             __nv_bfloat16* __restrict__ Cs,
             int N, int Ku64)
{
    extern __shared__ __align__(16) __nv_bfloat16 sm[];
    uint32_t sbase = smem_u32(sm);

    int tid  = threadIdx.x;
    int lane = tid & 31;
    int warp = tid >> 5;
    int wm = warp >> 2;
    int wn = warp & 3;
    int bm = blockIdx.x * 128;
    int bn = blockIdx.y * 128;
    int Astride = TERMS * Ku64 * 64;

    const char* gAbase = (const char*)(A + (size_t)bm * Astride);
    const char* gBbase = (const char*)(B + bn);

    uint32_t aFrag = (uint32_t)(((wm * 64 + (lane & 15)) * 72 + (lane >> 4) * 8) * 2);
    uint32_t bFrag = (uint32_t)(A_STG_B + ((lane & 15) * 136 + wn * 32 + (lane >> 4) * 8) * 2);

    float acc[4][4][4];
    #pragma unroll
    for (int i = 0; i < 4; i++)
        #pragma unroll
        for (int j = 0; j < 4; j++)
            #pragma unroll
            for (int k = 0; k < 4; k++) acc[i][j][k] = 0.f;

    int steps = TERMS * Ku64;

    auto load_stage = [&](int t) {
        uint32_t so = sbase + (uint32_t)(t % 3) * SSTG_B;
        int bs = (t < Ku64) ? t : t - Ku64;
        const char* aP = gAbase + (size_t)t * 128;
        const char* bP = gBbase + (size_t)bs * ((size_t)N * 128);
        #pragma unroll
        for (int j = 0; j < 4; j++) {
            int i = tid + j * 256;
            cp16(so + (uint32_t)(((i >> 3) * 72 + (i & 7) * 8) * 2),
                 aP + (size_t)(i >> 3) * Astride * 2 + (i & 7) * 16);
            cp16(so + (uint32_t)(A_STG_B + ((i >> 4) * 136 + (i & 15) * 8) * 2),
                 bP + (size_t)(i >> 4) * N * 2 + (i & 15) * 16);
        }
        asm volatile("cp.async.commit_group;" ::: "memory");
    };

    load_stage(0);
    if (steps > 1) load_stage(1);

    uint32_t af[2][16], bf[2][8];

    auto ldsA = [&](uint32_t* f, uint32_t stg, int kk) {
        #pragma unroll
        for (int mt = 0; mt < 4; mt++) {
            uint32_t addr = stg + aFrag + mt * (16 * 72 * 2) + kk * 32;
            LDSM4(f[mt * 4 + 0], f[mt * 4 + 1], f[mt * 4 + 2], f[mt * 4 + 3], addr);
        }
    };
    auto ldsB = [&](uint32_t* f, uint32_t stg, int kk) {
        #pragma unroll
        for (int p = 0; p < 2; p++) {
            uint32_t addr = stg + bFrag + p * 32 + kk * (16 * 136 * 2);
            LDSM4T(f[p * 4 + 0], f[p * 4 + 1], f[p * 4 + 2], f[p * 4 + 3], addr);
        }
    };

    for (int t = 0; t < steps; t++) {
        if (t + 1 < steps) asm volatile("cp.async.wait_group 1;" ::: "memory");
        else               asm volatile("cp.async.wait_group 0;" ::: "memory");
        __syncthreads();
        if (t + 2 < steps) load_stage(t + 2);

        uint32_t stg = sbase + (uint32_t)(t % 3) * SSTG_B;
        ldsA(af[0], stg, 0);
        ldsB(bf[0], stg, 0);
        #pragma unroll
        for (int kk = 0; kk < 4; kk++) {
            int cur = kk & 1, nxt = cur ^ 1;
            if (kk < 3) { ldsA(af[nxt], stg, kk + 1); ldsB(bf[nxt], stg, kk + 1); }
            #pragma unroll
            for (int mt = 0; mt < 4; mt++) {
                #pragma unroll
                for (int nt = 0; nt < 4; nt++) {
                    uint32_t b0 = bf[cur][(nt >> 1) * 4 + (nt & 1) * 2];
                    uint32_t b1 = bf[cur][(nt >> 1) * 4 + (nt & 1) * 2 + 1];
                    mma_op<F16>(acc[mt][nt], &af[cur][mt * 4], b0, b1);
                }
            }
        }
    }

    int row0 = bm + wm * 64;
    int col0 = bn + wn * 32;
    #pragma unroll
    for (int mt = 0; mt < 4; mt++) {
        #pragma unroll
        for (int nt = 0; nt < 4; nt++) {
            int r = row0 + mt * 16 + (lane >> 2);
            int c = col0 + nt * 8 + (lane & 3) * 2;
            #pragma unroll
            for (int half = 0; half < 2; half++) {
                int rr = r + half * 8;
                #pragma unroll
                for (int e = 0; e < 2; e++) {
                    float val = acc[mt][nt][half * 2 + e];
                    int cc = c + e;
                    if (BIAS) val += bias[cc];
                    if (GELU) val = 0.5f * val * (1.0f + erff(val * 0.70710678118654752f));
                    if (SPLITM == 2) {
                        __half* Ch = (__half*)Cs;
                        __half hi = __float2half_rn(val);
                        __half lo = __float2half_rn(val - __half2float(hi));
                        size_t base = (size_t)rr * (2 * (size_t)N);
                        Ch[base + cc] = hi;
                        Ch[base + N + cc] = lo;
                    } else if (SPLITM == 3) {
                        __half* Ch = (__half*)Cs;
                        Ch[(size_t)rr * N + cc] = __float2half_rn(val);
                    } else {
                        size_t off = (size_t)rr * N + cc;
                        if (RES) val += C[off];
                        C[off] = val;
                    }
                }
            }
        }
    }
}

// ---------------- tensor-core flash attention: QK 3-term bf16, PV 2-term fp16 --------
#define FLQ_E (64 * 200)
#define FLK_E (192 * 72)
#define FLV_E (64 * 72)
#define FL_SMEM ((FLQ_E + FLK_E + FLV_E) * 2)

__global__ void __launch_bounds__(128) flash_kernel(const __nv_bfloat16* __restrict__ Qsp,
                                                    const __nv_bfloat16* __restrict__ Ksp,
                                                    const __half* __restrict__ Vsp,
                                                    __half* __restrict__ ab) {
    extern __shared__ __align__(16) __nv_bfloat16 fsm[];
    uint32_t qsmem = smem_u32(fsm);
    uint32_t ksmem = qsmem + FLQ_E * 2;
    uint32_t vsmem = ksmem + FLK_E * 2;

    int br = gridDim.x - 1 - blockIdx.x;     // heavy blocks first
    int h  = blockIdx.y;
    int tid = threadIdx.x, lane = tid & 31, warp = tid >> 5;

    const char* qg = (const char*)(Qsp + ((size_t)h * 32 + br) * (64 * 192));
    #pragma unroll
    for (int l = 0; l < 12; l++) {
        int c = tid + l * 128;
        int row = c / 24, col = c - row * 24;
        cp16(qsmem + (uint32_t)(row * 400 + col * 16), qg + (size_t)row * 384 + col * 16);
    }
    asm volatile("cp.async.commit_group;" ::: "memory");
    asm volatile("cp.async.wait_group 0;" ::: "memory");
    __syncthreads();

    uint32_t qf[12][4];
    uint32_t qbase = qsmem + (uint32_t)(((warp * 16 + (lane & 15)) * 200 + (lane >> 4) * 8) * 2);
    #pragma unroll
    for (int s = 0; s < 12; s++)
        LDSM4(qf[s][0], qf[s][1], qf[s][2], qf[s][3], qbase + s * 32);

    uint32_t ksb = ksmem + (uint32_t)(((lane & 15) * 72 + (lane >> 4) * 8) * 2);
    uint32_t vsb = vsmem + (uint32_t)(((lane & 15) * 72 + (lane >> 4) * 8) * 2);

    float O[8][4];
    float run_max[2] = {-1e30f, -1e30f};
    float run_sum[2] = {0.f, 0.f};
    #pragma unroll
    for (int nt = 0; nt < 8; nt++)
        #pragma unroll
        for (int e = 0; e < 4; e++) O[nt][e] = 0.f;

    for (int kb = 0; kb <= br; kb++) {
        __syncthreads();
        const char* kg = (const char*)(Ksp + ((size_t)h * 32 + kb) * (192 * 64));
        const char* vg = (const char*)(Vsp + ((size_t)h * 32 + kb) * (64 * 64));
        #pragma unroll
        for (int l = 0; l < 12; l++) {
            int c = tid + l * 128;
            int row = c >> 3, col = c & 7;
            cp16(ksmem + (uint32_t)(row * 144 + col * 16), kg + (size_t)row * 128 + col * 16);
        }
        #pragma unroll
        for (int l = 0; l < 4; l++) {
            int c = tid + l * 128;
            int row = c >> 3, col = c & 7;
            cp16(vsmem + (uint32_t)(row * 144 + col * 16), vg + (size_t)row * 128 + col * 16);
        }
        asm volatile("cp.async.commit_group;" ::: "memory");
        asm volatile("cp.async.wait_group 0;" ::: "memory");
        __syncthreads();

        float S[8][4];
        #pragma unroll
        for (int nt = 0; nt < 8; nt++)
            #pragma unroll
            for (int e = 0; e < 4; e++) S[nt][e] = 0.f;
        #pragma unroll
        for (int s = 0; s < 12; s++) {
            uint32_t bfr[4][4];
            #pragma unroll
            for (int p = 0; p < 4; p++)
                LDSM4T(bfr[p][0], bfr[p][1], bfr[p][2], bfr[p][3],
                       ksb + p * 32 + s * (16 * 72 * 2));
            #pragma unroll
            for (int nt = 0; nt < 8; nt++) {
                uint32_t b0 = bfr[nt >> 1][(nt & 1) * 2];
                uint32_t b1 = bfr[nt >> 1][(nt & 1) * 2 + 1];
                mma_op<false>(S[nt], qf[s], b0, b1);
            }
        }

        if (kb == br) {
            #pragma unroll
            for (int nt = 0; nt < 8; nt++)
                #pragma unroll
                for (int e = 0; e < 4; e++) {
                    int rowl = warp * 16 + (lane >> 2) + (e >> 1) * 8;
                    int coll = nt * 8 + (lane & 3) * 2 + (e & 1);
                    if (coll > rowl) S[nt][e] = -1e30f;
                }
        }

        float alpha[2];
        #pragma unroll
        for (int half = 0; half < 2; half++) {
            float m = -1e30f;
            #pragma unroll
            for (int nt = 0; nt < 8; nt++)
                m = fmaxf(m, fmaxf(S[nt][half * 2], S[nt][half * 2 + 1]));
            m = fmaxf(m, __shfl_xor_sync(0xffffffffu, m, 1));
            m = fmaxf(m, __shfl_xor_sync(0xffffffffu, m, 2));
            float nm = fmaxf(run_max[half], m);
            alpha[half] = __expf(run_max[half] - nm);
            run_max[half] = nm;
            float ps = 0.f;
            #pragma unroll
            for (int nt = 0; nt < 8; nt++) {
                float p0 = __expf(S[nt][half * 2]     - nm);
                float p1 = __expf(S[nt][half * 2 + 1] - nm);
                S[nt][half * 2]     = p0;
                S[nt][half * 2 + 1] = p1;
                ps += p0 + p1;
            }
            ps += __shfl_xor_sync(0xffffffffu, ps, 1);
            ps += __shfl_xor_sync(0xffffffffu, ps, 2);
            run_sum[half] = run_sum[half] * alpha[half] + ps;
        }
        #pragma unroll
        for (int nt = 0; nt < 8; nt++) {
            O[nt][0] *= alpha[0]; O[nt][1] *= alpha[0];
            O[nt][2] *= alpha[1]; O[nt][3] *= alpha[1];
        }

        uint32_t phi[4][4], plo[4][4];
        #pragma unroll
        for (int t = 0; t < 4; t++) {
            #pragma unroll
            for (int g = 0; g < 2; g++) {
                float c0 = S[2 * t + g][0], c1 = S[2 * t + g][1];
                float c2 = S[2 * t + g][2], c3 = S[2 * t + g][3];
                __half h0 = __float2half_rn(c0);
                __half h1 = __float2half_rn(c1);
                __half h2 = __float2half_rn(c2);
                __half h3 = __float2half_rn(c3);
                __half2 p01 = __halves2half2(h0, h1);
                __half2 p23 = __halves2half2(h2, h3);
                phi[t][g * 2 + 0] = *(uint32_t*)&p01;
                phi[t][g * 2 + 1] = *(uint32_t*)&p23;
                plo[t][g * 2 + 0] = pack_f16(c0 - __half2float(h0), c1 - __half2float(h1));
                plo[t][g * 2 + 1] = pack_f16(c2 - __half2float(h2), c3 - __half2float(h3));
            }
        }

        #pragma unroll
        for (int s = 0; s < 8; s++) {
            uint32_t bfr[4][4];
            #pragma unroll
            for (int p = 0; p < 4; p++)
                LDSM4T(bfr[p][0], bfr[p][1], bfr[p][2], bfr[p][3],
                       vsb + p * 32 + (s & 3) * (16 * 72 * 2));
            const uint32_t* a = (s < 4) ? phi[s] : plo[s - 4];
            #pragma unroll
            for (int nt = 0; nt < 8; nt++) {
                uint32_t b0 = bfr[nt >> 1][(nt & 1) * 2];
                uint32_t b1 = bfr[nt >> 1][(nt & 1) * 2 + 1];
                mma_op<true>(O[nt], a, b0, b1);
            }
        }
    }

    float inv0 = 1.0f / run_sum[0];
    float inv1 = 1.0f / run_sum[1];
    #pragma unroll
    for (int half = 0; half < 2; half++) {
        int row = br * 64 + warp * 16 + (lane >> 2) + half * 8;
        size_t base = (size_t)row * (2 * DIM);
        float inv = half ? inv1 : inv0;
        #pragma unroll
        for (int nt = 0; nt < 8; nt++) {
            int col = h * DH + nt * 8 + (lane & 3) * 2;
            float v0 = O[nt][half * 2]     * inv;
            float v1 = O[nt][half * 2 + 1] * inv;
            __half h0 = __float2half_rn(v0);
            __half h1 = __float2half_rn(v1);
            __half l0 = __float2half_rn(v0 - __half2float(h0));
            __half l1 = __float2half_rn(v1 - __half2float(h1));
            *(__half2*)(ab + base + col)       = __halves2half2(h0, h1);
            *(__half2*)(ab + base + DIM + col) = __halves2half2(l0, l1);
        }
    }
}

// ---------------- launch ----------------
static inline void convw_f16_s(const float* src, __half* dst, long long K, long long N,
                               cudaStream_t st) {
    long long KN4 = K * N / 4;
    convw_f16_kernel<<<(unsigned)((KN4 + 255) / 256), 256, 0, st>>>((const float4*)src, dst, KN4);
}

#define BG_QKV   bgemm_kernel<2, true, false, false, false, 0>
#define BG_OUT   bgemm_kernel<2, true, false, true,  false, 0>
#define BG_FF1   bgemm_kernel<1, true, true,  false, true,  3>
#define BG_FF2   bgemm_kernel<1, true, true,  true,  false, 0>
#define BG_LOGIT bgemm_kernel<1, true, false, false, false, 0>

extern "C" void kernel_launch(void* const* d_in, const int* in_sizes, int n_in,
                              void* d_out, int out_size) {
    const int*   tokens      = (const int*)  d_in[0];
    const float* emb         = (const float*)d_in[1];
    const float* gamma_attn  = (const float*)d_in[2];
    const float* w_qkv       = (const float*)d_in[3];
    const float* w_out       = (const float*)d_in[4];
    const float* gamma_ff    = (const float*)d_in[5];
    const float* w_ff1       = (const float*)d_in[6];
    const float* b_ff1       = (const float*)d_in[7];
    const float* w_ff2       = (const float*)d_in[8];
    const float* b_ff2       = (const float*)d_in[9];
    const float* gamma_final = (const float*)d_in[10];
    const float* w_logits    = (const float*)d_in[11];
    float* out = (float*)d_out;

    float *x, *qkv;
    __nv_bfloat16 *ab, *ab2, *wb, *qs, *ks;
    __half *vs;
    cudaGetSymbolAddress((void**)&x,   g_x);
    cudaGetSymbolAddress((void**)&qkv, g_qkv);
    cudaGetSymbolAddress((void**)&ab,  g_ab);
    cudaGetSymbolAddress((void**)&ab2, g_ab2);
    cudaGetSymbolAddress((void**)&wb,  g_wb);
    cudaGetSymbolAddress((void**)&qs,  g_qs);
    cudaGetSymbolAddress((void**)&ks,  g_ks);
    cudaGetSymbolAddress((void**)&vs,  g_vs);

    cudaFuncSetAttribute(flash_kernel, cudaFuncAttributeMaxDynamicSharedMemorySize, FL_SMEM);
    cudaFuncSetAttribute(BG_QKV,   cudaFuncAttributeMaxDynamicSharedMemorySize, GEMM_SMEM);
    cudaFuncSetAttribute(BG_OUT,   cudaFuncAttributeMaxDynamicSharedMemorySize, GEMM_SMEM);
    cudaFuncSetAttribute(BG_FF1,   cudaFuncAttributeMaxDynamicSharedMemorySize, GEMM_SMEM);
    cudaFuncSetAttribute(BG_FF2,   cudaFuncAttributeMaxDynamicSharedMemorySize, GEMM_SMEM);
    cudaFuncSetAttribute(BG_LOGIT, cudaFuncAttributeMaxDynamicSharedMemorySize, GEMM_SMEM);

    // lazily-created side stream + events
    static cudaStream_t s2 = nullptr;
    static cudaEvent_t evFork;
    static cudaEvent_t evW[17];
    if (!s2) {
        cudaStreamCreateWithFlags(&s2, cudaStreamNonBlocking);
        cudaEventCreateWithFlags(&evFork, cudaEventDisableTiming);
        for (int i = 0; i < 17; i++)
            cudaEventCreateWithFlags(&evW[i], cudaEventDisableTiming);
    }

    // fork: weight conversions on s2
    cudaEventRecord(evFork, 0);
    cudaStreamWaitEvent(s2, evFork, 0);
    for (int l = 0; l < DEPTH; l++) {
        convw_f16_s(w_qkv + (size_t)l * DIM * 3 * DIM, (__half*)(wb + WB_QKV(l)), DIM, 3 * DIM, s2);
        cudaEventRecord(evW[4 * l + 0], s2);
        convw_f16_s(w_out + (size_t)l * DIM * DIM, (__half*)(wb + WB_OUT(l)), DIM, DIM, s2);
        cudaEventRecord(evW[4 * l + 1], s2);
        convw_f16_s(w_ff1 + (size_t)l * DIM * FFD, (__half*)(wb + WB_FF1(l)), DIM, FFD, s2);
        cudaEventRecord(evW[4 * l + 2], s2);
        convw_f16_s(w_ff2 + (size_t)l * FFD * DIM, (__half*)(wb + WB_FF2(l)), FFD, DIM, s2);
        cudaEventRecord(evW[4 * l + 3], s2);
    }
    convw_f16_s(w_logits, (__half*)(wb + WB_LOGITS), DIM, VOCAB, s2);
    cudaEventRecord(evW[16], s2);

    // main chain
    embed_kernel<<<SEQ * DIM / 256, 256>>>(tokens, emb, x);

    for (int l = 0; l < DEPTH; l++) {
        rmsnorm_split_f16_kernel<<<SEQ, 256>>>(x, gamma_attn + l * DIM, (__half*)ab);
        cudaStreamWaitEvent(0, evW[4 * l + 0], 0);
        BG_QKV<<<dim3(SEQ / 128, 3 * DIM / 128), 256, GEMM_SMEM>>>(
            ab, wb + WB_QKV(l), nullptr, qkv, nullptr, 3 * DIM, DIM / 64);
        qkvsplit_kernel<<<dim3(32, HEADS), 256>>>(qkv, qs, ks, vs);
        flash_kernel<<<dim3(SEQ / 64, HEADS), 128, FL_SMEM>>>(qs, ks, vs, (__half*)ab);
        cudaStreamWaitEvent(0, evW[4 * l + 1], 0);
        BG_OUT<<<dim3(SEQ / 128, DIM / 128), 256, GEMM_SMEM>>>(
            ab, wb + WB_OUT(l), nullptr, x, nullptr, DIM, DIM / 64);
        // --- feedforward block (1-term fp16) ---
        rmsnorm_f16_kernel<<<SEQ, 256>>>(x, gamma_ff + l * DIM, (__half*)ab);
        cudaStreamWaitEvent(0, evW[4 * l + 2], 0);
        BG_FF1<<<dim3(SEQ / 128, FFD / 128), 256, GEMM_SMEM>>>(
            ab, wb + WB_FF1(l), b_ff1 + (size_t)l * FFD, nullptr, ab2, FFD, DIM / 64);
        cudaStreamWaitEvent(0, evW[4 * l + 3], 0);
        BG_FF2<<<dim3(SEQ / 128, DIM / 128), 256, GEMM_SMEM>>>(
            ab2, wb + WB_FF2(l), b_ff2 + (size_t)l * DIM, x, nullptr, DIM, FFD / 64);
    }

    // final norm + fp16 1-term logits GEMM
    rmsnorm_f16_kernel<<<SEQ, 256>>>(x, gamma_final, (__half*)ab);
    cudaStreamWaitEvent(0, evW[16], 0);
    BG_LOGIT<<<dim3(SEQ / 128, VOCAB / 128), 256, GEMM_SMEM>>>(
        ab, wb + WB_LOGITS, nullptr, out, nullptr, VOCAB, DIM / 64);
}

// round 17
// speedup vs baseline: 1.4933x; 1.0843x over previous
#include <cuda_runtime.h>
#include <cuda_bf16.h>
#include <cuda_fp16.h>
#include <math.h>
#include <float.h>
#include <stdint.h>

// ---------------- problem constants ----------------
#define SEQ   2048
#define DIM   1024
#define DEPTH 4
#define HEADS 16
#define DH    64
#define FFD   4096
#define VOCAB 32000

// ---------------- scratch (static device globals) ----------------
__device__ float g_x   [SEQ * DIM];
__device__ float g_qkv [SEQ * 3 * DIM];
__device__ __nv_bfloat16 g_ab [SEQ * 3 * DIM];
__device__ __nv_bfloat16 g_ab2[SEQ * 3 * FFD];
__device__ __nv_bfloat16 g_wb [133431296ull];
__device__ __align__(16) __nv_bfloat16 g_qs[6291456ull];  // Q tiles [h][ib][64][192] bf16 3-term
__device__ __align__(16) __nv_bfloat16 g_ks[6291456ull];  // K tiles [h][jb][192][64] bf16 3-term
__device__ __align__(16) __half        g_vs[2097152ull];  // V tiles [h][jb][64][64]  fp16 hi

// weight offsets in g_wb (2-byte elements) — all fp16 hi-only
#define WB_QKV(l)  ((size_t)(l) * 6291456ull)
#define WB_OUT(l)  (25165824ull + (size_t)(l) * 2097152ull)
#define WB_FF1(l)  (33554432ull + (size_t)(l) * 8388608ull)
#define WB_FF2(l)  (67108864ull + (size_t)(l) * 8388608ull)
#define WB_LOGITS  100663296ull

// ---------------- helpers ----------------
__device__ __forceinline__ uint32_t smem_u32(const void* p) {
    return (uint32_t)__cvta_generic_to_shared(p);
}
__device__ __forceinline__ void cp16(uint32_t s, const void* g) {
    asm volatile("cp.async.cg.shared.global [%0], [%1], 16;" :: "r"(s), "l"(g));
}
__device__ __forceinline__ uint32_t pack_f16(float a, float b) {
    __half2 t = __floats2half2_rn(a, b);
    return *(uint32_t*)&t;
}

// ---------------- weight conv fp16 (hi only) ----------------
__global__ void __launch_bounds__(256) convw_f16_kernel(const float4* __restrict__ w,
                                                        __half* __restrict__ o,
                                                        long long KN4) {
    long long idx = (long long)blockIdx.x * 256 + threadIdx.x;
    if (idx >= KN4) return;
    float4 v = w[idx];
    union { __half u[4]; uint2 p; } h4;
    h4.u[0] = __float2half_rn(v.x); h4.u[1] = __float2half_rn(v.y);
    h4.u[2] = __float2half_rn(v.z); h4.u[3] = __float2half_rn(v.w);
    *(uint2*)(o + 4 * idx) = h4.p;
}

// ---------------- embed ----------------
__global__ void __launch_bounds__(256) embed_kernel(const int* __restrict__ tokens,
                                                    const float* __restrict__ emb,
                                                    float* __restrict__ x) {
    int idx = blockIdx.x * 256 + threadIdx.x;
    int row = idx >> 10;
    int d   = idx & 1023;
    x[idx] = emb[(size_t)tokens[row] * DIM + d];
}

// ---------------- rmsnorm fp16 1-term ----------------
__global__ void __launch_bounds__(256) rmsnorm_f16_kernel(const float* __restrict__ x,
                                                          const float* __restrict__ gamma,
                                                          __half* __restrict__ ab) {
    int row = blockIdx.x;
    const float* xr = x + (size_t)row * DIM;
    float ss = 0.f;
    for (int i = threadIdx.x; i < DIM; i += 256) { float v = xr[i]; ss += v * v; }
    __shared__ float red[256];
    red[threadIdx.x] = ss;
    __syncthreads();
    for (int s = 128; s > 0; s >>= 1) {
        if (threadIdx.x < s) red[threadIdx.x] += red[threadIdx.x + s];
        __syncthreads();
    }
    float scale = 32.0f / fmaxf(sqrtf(red[0]), 1e-12f);
    __half* ar = ab + (size_t)row * DIM;
    for (int i = threadIdx.x; i < DIM; i += 256)
        ar[i] = __float2half_rn(xr[i] * scale * gamma[i]);
}

// ---------------- fused Q/K/V split (rotary fused, shared trig) ----------------
#define L2_10000 13.287712379549449f
__global__ void __launch_bounds__(256) qkvsplit_kernel(const float* __restrict__ qkv,
                                                       __nv_bfloat16* __restrict__ Qsp,
                                                       __nv_bfloat16* __restrict__ Ksp,
                                                       __half* __restrict__ Vsp) {
    __shared__ float kt_s[64][65];
    int blk = blockIdx.x, h = blockIdx.y;
    int tid = threadIdx.x;
    __nv_bfloat16* qt = Qsp + ((size_t)h * 32 + blk) * (64 * 192);
    __nv_bfloat16* kt = Ksp + ((size_t)h * 32 + blk) * (192 * 64);
    __half*        vt = Vsp + ((size_t)h * 32 + blk) * (64 * 64);
    #pragma unroll
    for (int l = 0; l < 16; l++) {
        int e = tid + l * 256;
        int i = e >> 6, d = e & 63;
        int pos = blk * 64 + i;
        const float* base = qkv + (size_t)pos * (3 * DIM);
        int j = d & 31;
        float inv = exp2f((float)j * (-L2_10000 / 32.0f));
        float fr = (float)pos * inv;
        float c, s;
        sincosf(fr, &s, &c);
        {
            const float* qrow = base + h * DH;
            float x = qrow[d], other = qrow[d ^ 32];
            float val = ((d < 32) ? (x * c - other * s) : (x * c + other * s)) * 0.125f;
            __nv_bfloat16 hi = __float2bfloat16_rn(val);
            __nv_bfloat16 lo = __float2bfloat16_rn(val - __bfloat162float(hi));
            qt[(size_t)i * 192 + d]       = hi;
            qt[(size_t)i * 192 + 64 + d]  = lo;
            qt[(size_t)i * 192 + 128 + d] = hi;
        }
        {
            const float* krow = base + (HEADS + h) * DH;
            float x = krow[d], other = krow[d ^ 32];
            kt_s[d][i] = (d < 32) ? (x * c - other * s) : (x * c + other * s);
        }
        vt[(size_t)i * 64 + d] = __float2half_rn(base[(2 * HEADS + h) * DH + d]);
    }
    __syncthreads();
    #pragma unroll
    for (int l = 0; l < 16; l++) {
        int e = tid + l * 256;
        int d = e >> 6, jj = e & 63;
        float val = kt_s[d][jj];
        __nv_bfloat16 hi = __float2bfloat16_rn(val);
        __nv_bfloat16 lo = __float2bfloat16_rn(val - __bfloat162float(hi));
        kt[(size_t)d * 64 + jj]         = hi;
        kt[(size_t)(64 + d) * 64 + jj]  = hi;
        kt[(size_t)(128 + d) * 64 + jj] = lo;
    }
}

// ---------------- mma primitives ----------------
#define LDSM4(R0,R1,R2,R3,addr) \
    asm volatile("ldmatrix.sync.aligned.m8n8.x4.shared.b16 {%0,%1,%2,%3},[%4];" \
        : "=r"(R0),"=r"(R1),"=r"(R2),"=r"(R3) : "r"(addr))
#define LDSM4T(R0,R1,R2,R3,addr) \
    asm volatile("ldmatrix.sync.aligned.m8n8.x4.trans.shared.b16 {%0,%1,%2,%3},[%4];" \
        : "=r"(R0),"=r"(R1),"=r"(R2),"=r"(R3) : "r"(addr))

template<bool F16>
__device__ __forceinline__ void mma_op(float* d, const uint32_t* a, uint32_t b0, uint32_t b1) {
    if (F16)
        asm volatile("mma.sync.aligned.m16n8k16.row.col.f32.f16.f16.f32 "
            "{%0,%1,%2,%3},{%4,%5,%6,%7},{%8,%9},{%0,%1,%2,%3};"
            : "+f"(d[0]),"+f"(d[1]),"+f"(d[2]),"+f"(d[3])
            : "r"(a[0]),"r"(a[1]),"r"(a[2]),"r"(a[3]),"r"(b0),"r"(b1));
    else
        asm volatile("mma.sync.aligned.m16n8k16.row.col.f32.bf16.bf16.f32 "
            "{%0,%1,%2,%3},{%4,%5,%6,%7},{%8,%9},{%0,%1,%2,%3};"
            : "+f"(d[0]),"+f"(d[1]),"+f"(d[2]),"+f"(d[3])
            : "r"(a[0]),"r"(a[1]),"r"(a[2]),"r"(a[3]),"r"(b0),"r"(b1));
}

// ---------------- tensor-core GEMM (K-chunk 64, 3 stages, frag dbuf) ----
// SPLITM: 0 = fp32 C (optional RES), 2 = fp16 2-term A'-format, 3 = fp16 1-term
#define A_STG_B 18432
#define B_STG_B 17408
#define SSTG_B  (A_STG_B + B_STG_B)
#define GEMM_SMEM (3 * SSTG_B)

template<int TERMS, bool F16, bool BIAS, bool RES, bool GELU, int SPLITM>
__global__ void __launch_bounds__(256, 2)
bgemm_kernel(const __nv_bfloat16* __restrict__ A,
             const __nv_bfloat16* __restrict__ B,
             const float* __restrict__ bias,
             float* __restrict__ C,
             __nv_bfloat16* __restrict__ Cs,
             int N, int Ku64)
{
    extern __shared__ __align__(16) __nv_bfloat16 sm[];
    uint32_t sbase = smem_u32(sm);

    int tid  = threadIdx.x;
    int lane = tid & 31;
    int warp = tid >> 5;
    int wm = warp >> 2;
    int wn = warp & 3;
    int bm = blockIdx.x * 128;
    int bn = blockIdx.y * 128;
    int Astride = TERMS * Ku64 * 64;

    const char* gAbase = (const char*)(A + (size_t)bm * Astride);
    const char* gBbase = (const char*)(B + bn);

    uint32_t aFrag = (uint32_t)(((wm * 64 + (lane & 15)) * 72 + (lane >> 4) * 8) * 2);
    uint32_t bFrag = (uint32_t)(A_STG_B + ((lane & 15) * 136 + wn * 32 + (lane >> 4) * 8) * 2);

    float acc[4][4][4];
    #pragma unroll
    for (int i = 0; i < 4; i++)
        #pragma unroll
        for (int j = 0; j < 4; j++)
            #pragma unroll
            for (int k = 0; k < 4; k++) acc[i][j][k] = 0.f;

    int steps = TERMS * Ku64;

    auto load_stage = [&](int t) {
        uint32_t so = sbase + (uint32_t)(t % 3) * SSTG_B;
        int bs = (t < Ku64) ? t : t - Ku64;
        const char* aP = gAbase + (size_t)t * 128;
        const char* bP = gBbase + (size_t)bs * ((size_t)N * 128);
        #pragma unroll
        for (int j = 0; j < 4; j++) {
            int i = tid + j * 256;
            cp16(so + (uint32_t)(((i >> 3) * 72 + (i & 7) * 8) * 2),
                 aP + (size_t)(i >> 3) * Astride * 2 + (i & 7) * 16);
            cp16(so + (uint32_t)(A_STG_B + ((i >> 4) * 136 + (i & 15) * 8) * 2),
                 bP + (size_t)(i >> 4) * N * 2 + (i & 15) * 16);
        }
        asm volatile("cp.async.commit_group;" ::: "memory");
    };

    load_stage(0);
    if (steps > 1) load_stage(1);

    uint32_t af[2][16], bf[2][8];

    auto ldsA = [&](uint32_t* f, uint32_t stg, int kk) {
        #pragma unroll
        for (int mt = 0; mt < 4; mt++) {
            uint32_t addr = stg + aFrag + mt * (16 * 72 * 2) + kk * 32;
            LDSM4(f[mt * 4 + 0], f[mt * 4 + 1], f[mt * 4 + 2], f[mt * 4 + 3], addr);
        }
    };
    auto ldsB = [&](uint32_t* f, uint32_t stg, int kk) {
        #pragma unroll
        for (int p = 0; p < 2; p++) {
            uint32_t addr = stg + bFrag + p * 32 + kk * (16 * 136 * 2);
            LDSM4T(f[p * 4 + 0], f[p * 4 + 1], f[p * 4 + 2], f[p * 4 + 3], addr);
        }
    };

    for (int t = 0; t < steps; t++) {
        if (t + 1 < steps) asm volatile("cp.async.wait_group 1;" ::: "memory");
        else               asm volatile("cp.async.wait_group 0;" ::: "memory");
        __syncthreads();
        if (t + 2 < steps) load_stage(t + 2);

        uint32_t stg = sbase + (uint32_t)(t % 3) * SSTG_B;
        ldsA(af[0], stg, 0);
        ldsB(bf[0], stg, 0);
        #pragma unroll
        for (int kk = 0; kk < 4; kk++) {
            int cur = kk & 1, nxt = cur ^ 1;
            if (kk < 3) { ldsA(af[nxt], stg, kk + 1); ldsB(bf[nxt], stg, kk + 1); }
            #pragma unroll
            for (int mt = 0; mt < 4; mt++) {
                #pragma unroll
                for (int nt = 0; nt < 4; nt++) {
                    uint32_t b0 = bf[cur][(nt >> 1) * 4 + (nt & 1) * 2];
                    uint32_t b1 = bf[cur][(nt >> 1) * 4 + (nt & 1) * 2 + 1];
                    mma_op<F16>(acc[mt][nt], &af[cur][mt * 4], b0, b1);
                }
            }
        }
    }

    int row0 = bm + wm * 64;
    int col0 = bn + wn * 32;
    #pragma unroll
    for (int mt = 0; mt < 4; mt++) {
        #pragma unroll
        for (int nt = 0; nt < 4; nt++) {
            int r = row0 + mt * 16 + (lane >> 2);
            int c = col0 + nt * 8 + (lane & 3) * 2;
            #pragma unroll
            for (int half = 0; half < 2; half++) {
                int rr = r + half * 8;
                #pragma unroll
                for (int e = 0; e < 2; e++) {
                    float val = acc[mt][nt][half * 2 + e];
                    int cc = c + e;
                    if (BIAS) val += bias[cc];
                    if (GELU) val = 0.5f * val * (1.0f + erff(val * 0.70710678118654752f));
                    if (SPLITM == 2) {
                        __half* Ch = (__half*)Cs;
                        __half hi = __float2half_rn(val);
                        __half lo = __float2half_rn(val - __half2float(hi));
                        size_t base = (size_t)rr * (2 * (size_t)N);
                        Ch[base + cc] = hi;
                        Ch[base + N + cc] = lo;
                    } else if (SPLITM == 3) {
                        __half* Ch = (__half*)Cs;
                        Ch[(size_t)rr * N + cc] = __float2half_rn(val);
                    } else {
                        size_t off = (size_t)rr * N + cc;
                        if (RES) val += C[off];
                        C[off] = val;
                    }
                }
            }
        }
    }
}

// ---------------- tensor-core flash attention: QK 3-term bf16, PV 2-term fp16 --------
#define FLQ_E (64 * 200)
#define FLK_E (192 * 72)
#define FLV_E (64 * 72)
#define FL_SMEM ((FLQ_E + FLK_E + FLV_E) * 2)

__global__ void __launch_bounds__(128) flash_kernel(const __nv_bfloat16* __restrict__ Qsp,
                                                    const __nv_bfloat16* __restrict__ Ksp,
                                                    const __half* __restrict__ Vsp,
                                                    __half* __restrict__ ab) {
    extern __shared__ __align__(16) __nv_bfloat16 fsm[];
    uint32_t qsmem = smem_u32(fsm);
    uint32_t ksmem = qsmem + FLQ_E * 2;
    uint32_t vsmem = ksmem + FLK_E * 2;

    int br = gridDim.x - 1 - blockIdx.x;     // heavy blocks first
    int h  = blockIdx.y;
    int tid = threadIdx.x, lane = tid & 31, warp = tid >> 5;

    const char* qg = (const char*)(Qsp + ((size_t)h * 32 + br) * (64 * 192));
    #pragma unroll
    for (int l = 0; l < 12; l++) {
        int c = tid + l * 128;
        int row = c / 24, col = c - row * 24;
        cp16(qsmem + (uint32_t)(row * 400 + col * 16), qg + (size_t)row * 384 + col * 16);
    }
    asm volatile("cp.async.commit_group;" ::: "memory");
    asm volatile("cp.async.wait_group 0;" ::: "memory");
    __syncthreads();

    uint32_t qf[12][4];
    uint32_t qbase = qsmem + (uint32_t)(((warp * 16 + (lane & 15)) * 200 + (lane >> 4) * 8) * 2);
    #pragma unroll
    for (int s = 0; s < 12; s++)
        LDSM4(qf[s][0], qf[s][1], qf[s][2], qf[s][3], qbase + s * 32);

    uint32_t ksb = ksmem + (uint32_t)(((lane & 15) * 72 + (lane >> 4) * 8) * 2);
    uint32_t vsb = vsmem + (uint32_t)(((lane & 15) * 72 + (lane >> 4) * 8) * 2);

    float O[8][4];
    float run_max[2] = {-1e30f, -1e30f};
    float run_sum[2] = {0.f, 0.f};
    #pragma unroll
    for (int nt = 0; nt < 8; nt++)
        #pragma unroll
        for (int e = 0; e < 4; e++) O[nt][e] = 0.f;

    for (int kb = 0; kb <= br; kb++) {
        __syncthreads();
        const char* kg = (const char*)(Ksp + ((size_t)h * 32 + kb) * (192 * 64));
        const char* vg = (const char*)(Vsp + ((size_t)h * 32 + kb) * (64 * 64));
        #pragma unroll
        for (int l = 0; l < 12; l++) {
            int c = tid + l * 128;
            int row = c >> 3, col = c & 7;
            cp16(ksmem + (uint32_t)(row * 144 + col * 16), kg + (size_t)row * 128 + col * 16);
        }
        #pragma unroll
        for (int l = 0; l < 4; l++) {
            int c = tid + l * 128;
            int row = c >> 3, col = c & 7;
            cp16(vsmem + (uint32_t)(row * 144 + col * 16), vg + (size_t)row * 128 + col * 16);
        }
        asm volatile("cp.async.commit_group;" ::: "memory");
        asm volatile("cp.async.wait_group 0;" ::: "memory");
        __syncthreads();

        float S[8][4];
        #pragma unroll
        for (int nt = 0; nt < 8; nt++)
            #pragma unroll
            for (int e = 0; e < 4; e++) S[nt][e] = 0.f;
        #pragma unroll
        for (int s = 0; s < 12; s++) {
            uint32_t bfr[4][4];
            #pragma unroll
            for (int p = 0; p < 4; p++)
                LDSM4T(bfr[p][0], bfr[p][1], bfr[p][2], bfr[p][3],
                       ksb + p * 32 + s * (16 * 72 * 2));
            #pragma unroll
            for (int nt = 0; nt < 8; nt++) {
                uint32_t b0 = bfr[nt >> 1][(nt & 1) * 2];
                uint32_t b1 = bfr[nt >> 1][(nt & 1) * 2 + 1];
                mma_op<false>(S[nt], qf[s], b0, b1);
            }
        }

        if (kb == br) {
            #pragma unroll
            for (int nt = 0; nt < 8; nt++)
                #pragma unroll
                for (int e = 0; e < 4; e++) {
                    int rowl = warp * 16 + (lane >> 2) + (e >> 1) * 8;
                    int coll = nt * 8 + (lane & 3) * 2 + (e & 1);
                    if (coll > rowl) S[nt][e] = -1e30f;
                }
        }

        float alpha[2];
        #pragma unroll
        for (int half = 0; half < 2; half++) {
            float m = -1e30f;
            #pragma unroll
            for (int nt = 0; nt < 8; nt++)
                m = fmaxf(m, fmaxf(S[nt][half * 2], S[nt][half * 2 + 1]));
            m = fmaxf(m, __shfl_xor_sync(0xffffffffu, m, 1));
            m = fmaxf(m, __shfl_xor_sync(0xffffffffu, m, 2));
            float nm = fmaxf(run_max[half], m);
            alpha[half] = __expf(run_max[half] - nm);
            run_max[half] = nm;
            float ps = 0.f;
            #pragma unroll
            for (int nt = 0; nt < 8; nt++) {
                float p0 = __expf(S[nt][half * 2]     - nm);
                float p1 = __expf(S[nt][half * 2 + 1] - nm);
                S[nt][half * 2]     = p0;
                S[nt][half * 2 + 1] = p1;
                ps += p0 + p1;
            }
            ps += __shfl_xor_sync(0xffffffffu, ps, 1);
            ps += __shfl_xor_sync(0xffffffffu, ps, 2);
            run_sum[half] = run_sum[half] * alpha[half] + ps;
        }
        #pragma unroll
        for (int nt = 0; nt < 8; nt++) {
            O[nt][0] *= alpha[0]; O[nt][1] *= alpha[0];
            O[nt][2] *= alpha[1]; O[nt][3] *= alpha[1];
        }

        uint32_t phi[4][4], plo[4][4];
        #pragma unroll
        for (int t = 0; t < 4; t++) {
            #pragma unroll
            for (int g = 0; g < 2; g++) {
                float c0 = S[2 * t + g][0], c1 = S[2 * t + g][1];
                float c2 = S[2 * t + g][2], c3 = S[2 * t + g][3];
                __half h0 = __float2half_rn(c0);
                __half h1 = __float2half_rn(c1);
                __half h2 = __float2half_rn(c2);
                __half h3 = __float2half_rn(c3);
                __half2 p01 = __halves2half2(h0, h1);
                __half2 p23 = __halves2half2(h2, h3);
                phi[t][g * 2 + 0] = *(uint32_t*)&p01;
                phi[t][g * 2 + 1] = *(uint32_t*)&p23;
                plo[t][g * 2 + 0] = pack_f16(c0 - __half2float(h0), c1 - __half2float(h1));
                plo[t][g * 2 + 1] = pack_f16(c2 - __half2float(h2), c3 - __half2float(h3));
            }
        }

        #pragma unroll
        for (int s = 0; s < 8; s++) {
            uint32_t bfr[4][4];
            #pragma unroll
            for (int p = 0; p < 4; p++)
                LDSM4T(bfr[p][0], bfr[p][1], bfr[p][2], bfr[p][3],
                       vsb + p * 32 + (s & 3) * (16 * 72 * 2));
            const uint32_t* a = (s < 4) ? phi[s] : plo[s - 4];
            #pragma unroll
            for (int nt = 0; nt < 8; nt++) {
                uint32_t b0 = bfr[nt >> 1][(nt & 1) * 2];
                uint32_t b1 = bfr[nt >> 1][(nt & 1) * 2 + 1];
                mma_op<true>(O[nt], a, b0, b1);
            }
        }
    }

    float inv0 = 1.0f / run_sum[0];
    float inv1 = 1.0f / run_sum[1];
    #pragma unroll
    for (int half = 0; half < 2; half++) {
        int row = br * 64 + warp * 16 + (lane >> 2) + half * 8;
        size_t base = (size_t)row * (2 * DIM);
        float inv = half ? inv1 : inv0;
        #pragma unroll
        for (int nt = 0; nt < 8; nt++) {
            int col = h * DH + nt * 8 + (lane & 3) * 2;
            float v0 = O[nt][half * 2]     * inv;
            float v1 = O[nt][half * 2 + 1] * inv;
            __half h0 = __float2half_rn(v0);
            __half h1 = __float2half_rn(v1);
            __half l0 = __float2half_rn(v0 - __half2float(h0));
            __half l1 = __float2half_rn(v1 - __half2float(h1));
            *(__half2*)(ab + base + col)       = __halves2half2(h0, h1);
            *(__half2*)(ab + base + DIM + col) = __halves2half2(l0, l1);
        }
    }
}

// ---------------- launch ----------------
static inline void convw_f16_s(const float* src, __half* dst, long long K, long long N,
                               cudaStream_t st) {
    long long KN4 = K * N / 4;
    convw_f16_kernel<<<(unsigned)((KN4 + 255) / 256), 256, 0, st>>>((const float4*)src, dst, KN4);
}

#define BG_QKV   bgemm_kernel<1, true, false, false, false, 0>
#define BG_OUT   bgemm_kernel<2, true, false, true,  false, 0>
#define BG_FF1   bgemm_kernel<1, true, true,  false, true,  3>
#define BG_FF2   bgemm_kernel<1, true, true,  true,  false, 0>
#define BG_LOGIT bgemm_kernel<1, true, false, false, false, 0>

extern "C" void kernel_launch(void* const* d_in, const int* in_sizes, int n_in,
                              void* d_out, int out_size) {
    const int*   tokens      = (const int*)  d_in[0];
    const float* emb         = (const float*)d_in[1];
    const float* gamma_attn  = (const float*)d_in[2];
    const float* w_qkv       = (const float*)d_in[3];
    const float* w_out       = (const float*)d_in[4];
    const float* gamma_ff    = (const float*)d_in[5];
    const float* w_ff1       = (const float*)d_in[6];
    const float* b_ff1       = (const float*)d_in[7];
    const float* w_ff2       = (const float*)d_in[8];
    const float* b_ff2       = (const float*)d_in[9];
    const float* gamma_final = (const float*)d_in[10];
    const float* w_logits    = (const float*)d_in[11];
    float* out = (float*)d_out;

    float *x, *qkv;
    __nv_bfloat16 *ab, *ab2, *wb, *qs, *ks;
    __half *vs;
    cudaGetSymbolAddress((void**)&x,   g_x);
    cudaGetSymbolAddress((void**)&qkv, g_qkv);
    cudaGetSymbolAddress((void**)&ab,  g_ab);
    cudaGetSymbolAddress((void**)&ab2, g_ab2);
    cudaGetSymbolAddress((void**)&wb,  g_wb);
    cudaGetSymbolAddress((void**)&qs,  g_qs);
    cudaGetSymbolAddress((void**)&ks,  g_ks);
    cudaGetSymbolAddress((void**)&vs,  g_vs);

    cudaFuncSetAttribute(flash_kernel, cudaFuncAttributeMaxDynamicSharedMemorySize, FL_SMEM);
    cudaFuncSetAttribute(BG_QKV,   cudaFuncAttributeMaxDynamicSharedMemorySize, GEMM_SMEM);
    cudaFuncSetAttribute(BG_OUT,   cudaFuncAttributeMaxDynamicSharedMemorySize, GEMM_SMEM);
    cudaFuncSetAttribute(BG_FF1,   cudaFuncAttributeMaxDynamicSharedMemorySize, GEMM_SMEM);
    cudaFuncSetAttribute(BG_FF2,   cudaFuncAttributeMaxDynamicSharedMemorySize, GEMM_SMEM);
    cudaFuncSetAttribute(BG_LOGIT, cudaFuncAttributeMaxDynamicSharedMemorySize, GEMM_SMEM);

    // lazily-created side stream + events
    static cudaStream_t s2 = nullptr;
    static cudaEvent_t evFork;
    static cudaEvent_t evW[17];
    if (!s2) {
        cudaStreamCreateWithFlags(&s2, cudaStreamNonBlocking);
        cudaEventCreateWithFlags(&evFork, cudaEventDisableTiming);
        for (int i = 0; i < 17; i++)
            cudaEventCreateWithFlags(&evW[i], cudaEventDisableTiming);
    }

    // fork: weight conversions on s2
    cudaEventRecord(evFork, 0);
    cudaStreamWaitEvent(s2, evFork, 0);
    for (int l = 0; l < DEPTH; l++) {
        convw_f16_s(w_qkv + (size_t)l * DIM * 3 * DIM, (__half*)(wb + WB_QKV(l)), DIM, 3 * DIM, s2);
        cudaEventRecord(evW[4 * l + 0], s2);
        convw_f16_s(w_out + (size_t)l * DIM * DIM, (__half*)(wb + WB_OUT(l)), DIM, DIM, s2);
        cudaEventRecord(evW[4 * l + 1], s2);
        convw_f16_s(w_ff1 + (size_t)l * DIM * FFD, (__half*)(wb + WB_FF1(l)), DIM, FFD, s2);
        cudaEventRecord(evW[4 * l + 2], s2);
        convw_f16_s(w_ff2 + (size_t)l * FFD * DIM, (__half*)(wb + WB_FF2(l)), FFD, DIM, s2);
        cudaEventRecord(evW[4 * l + 3], s2);
    }
    convw_f16_s(w_logits, (__half*)(wb + WB_LOGITS), DIM, VOCAB, s2);
    cudaEventRecord(evW[16], s2);

    // main chain
    embed_kernel<<<SEQ * DIM / 256, 256>>>(tokens, emb, x);

    for (int l = 0; l < DEPTH; l++) {
        rmsnorm_f16_kernel<<<SEQ, 256>>>(x, gamma_attn + l * DIM, (__half*)ab);
        cudaStreamWaitEvent(0, evW[4 * l + 0], 0);
        BG_QKV<<<dim3(SEQ / 128, 3 * DIM / 128), 256, GEMM_SMEM>>>(
            ab, wb + WB_QKV(l), nullptr, qkv, nullptr, 3 * DIM, DIM / 64);
        qkvsplit_kernel<<<dim3(32, HEADS), 256>>>(qkv, qs, ks, vs);
        flash_kernel<<<dim3(SEQ / 64, HEADS), 128, FL_SMEM>>>(qs, ks, vs, (__half*)ab);
        cudaStreamWaitEvent(0, evW[4 * l + 1], 0);
        BG_OUT<<<dim3(SEQ / 128, DIM / 128), 256, GEMM_SMEM>>>(
            ab, wb + WB_OUT(l), nullptr, x, nullptr, DIM, DIM / 64);
        // --- feedforward block (1-term fp16) ---
        rmsnorm_f16_kernel<<<SEQ, 256>>>(x, gamma_ff + l * DIM, (__half*)ab);
        cudaStreamWaitEvent(0, evW[4 * l + 2], 0);
        BG_FF1<<<dim3(SEQ / 128, FFD / 128), 256, GEMM_SMEM>>>(
            ab, wb + WB_FF1(l), b_ff1 + (size_t)l * FFD, nullptr, ab2, FFD, DIM / 64);
        cudaStreamWaitEvent(0, evW[4 * l + 3], 0);
        BG_FF2<<<dim3(SEQ / 128, DIM / 128), 256, GEMM_SMEM>>>(
            ab2, wb + WB_FF2(l), b_ff2 + (size_t)l * DIM, x, nullptr, DIM, FFD / 64);
    }

    // final norm + fp16 1-term logits GEMM
    rmsnorm_f16_kernel<<<SEQ, 256>>>(x, gamma_final, (__half*)ab);
    cudaStreamWaitEvent(0, evW[16], 0);
    BG_LOGIT<<<dim3(SEQ / 128, VOCAB / 128), 256, GEMM_SMEM>>>(
        ab, wb + WB_LOGITS, nullptr, out, nullptr, VOCAB, DIM / 64);
}